// round 10
// baseline (speedup 1.0000x reference)
#include <cuda_runtime.h>

#define CC 64
#define TT 512
#define VV 25
#define DD 16
#define SS 256
#define NVB 400

#define XP_STR   68
#define KKT_STR  516
#define OFF_KKT  34816
#define OFF_QA   43072
#define OFF_A    47168
#define OFF_KB   55616
#define OFF_RED  55632
#define SMEM_FLOATS 55696      // 222784 bytes

typedef unsigned long long u64;

__device__ __forceinline__ u64 pk2(float a, float b) {
    u64 r; asm("mov.b64 %0, {%1,%2};" : "=l"(r) : "f"(a), "f"(b)); return r;
}
__device__ __forceinline__ u64 f2(u64 a, u64 b, u64 c) {
    u64 d; asm("fma.rn.f32x2 %0, %1, %2, %3;" : "=l"(d) : "l"(a), "l"(b), "l"(c)); return d;
}
__device__ __forceinline__ u64 ad2(u64 a, u64 b) {
    u64 d; asm("add.rn.f32x2 %0, %1, %2;" : "=l"(d) : "l"(a), "l"(b)); return d;
}
__device__ __forceinline__ float2 up2(u64 a) {
    float lo, hi; asm("mov.b64 {%0,%1}, %2;" : "=f"(lo), "=f"(hi) : "l"(a));
    return make_float2(lo, hi);
}

__global__ void __launch_bounds__(512, 1) tgat5_kernel(
    const float* __restrict__ x, const float* __restrict__ W,
    const float* __restrict__ alpha, const float* __restrict__ phi,
    const float* __restrict__ karr, float* __restrict__ out)
{
    extern __shared__ float sm[];
    float* s_xp  = sm;                 // [512][68]
    float* s_kkT = sm + OFF_KKT;       // [16][516]
    float* s_qa  = sm + OFF_QA;        // [256][16]   (= sW during phase 1)
    float* s_A   = sm + OFF_A;         // 8448-float overlay
    float* s_kb  = sm + OFF_KB;        // band kernel
    float* s_red = sm + OFF_RED;       // [16 rows][4 quarters]

    const int tid = threadIdx.x;
    const int nv = blockIdx.x;
    const int n = nv / VV, v = nv - n * VV;

    // ---------- phase 0: W -> smem (qa region), band kernel ----------
    float* sW = s_qa;
    for (int i = tid; i < CC * CC; i += 512) sW[i] = W[i];
    if (tid < 16) s_kb[tid] = (tid < 9) ? karr[tid] : 0.0f;

    // ---------- phase 1: xp = x^T W, 4 chunks of 128 t ----------
    const float* xb = x + ((size_t)n * CC * TT) * VV + v;
    float* xs = s_A;                   // [64][132]
    float xr[16];
    #pragma unroll
    for (int kx = 0; kx < 16; kx++) {
        int idx = tid + kx * 512; int c = idx >> 7, t = idx & 127;
        xr[kx] = __ldg(xb + ((size_t)c * TT + t) * VV);
    }
    const int tg = tid >> 4, dg = tid & 15;
    for (int ch = 0; ch < 4; ch++) {
        if (ch > 0) __syncthreads();
        #pragma unroll
        for (int kx = 0; kx < 16; kx++) {
            int idx = tid + kx * 512; int c = idx >> 7, t = idx & 127;
            xs[c * 132 + t] = xr[kx];
        }
        __syncthreads();
        if (ch < 3) {
            int tb = (ch + 1) * 128;
            #pragma unroll
            for (int kx = 0; kx < 16; kx++) {
                int idx = tid + kx * 512; int c = idx >> 7, t = idx & 127;
                xr[kx] = __ldg(xb + ((size_t)c * TT + tb + t) * VV);
            }
        }
        u64 acc[4][2];
        #pragma unroll
        for (int i = 0; i < 4; i++) { acc[i][0] = pk2(0.f, 0.f); acc[i][1] = acc[i][0]; }
        #pragma unroll 8
        for (int c = 0; c < 64; c++) {
            float4 xv = *(const float4*)(xs + c * 132 + tg * 4);
            ulonglong2 wv = *(const ulonglong2*)(sW + c * 64 + dg * 4);
            u64 x0 = pk2(xv.x, xv.x), x1 = pk2(xv.y, xv.y);
            u64 x2 = pk2(xv.z, xv.z), x3 = pk2(xv.w, xv.w);
            acc[0][0] = f2(x0, wv.x, acc[0][0]); acc[0][1] = f2(x0, wv.y, acc[0][1]);
            acc[1][0] = f2(x1, wv.x, acc[1][0]); acc[1][1] = f2(x1, wv.y, acc[1][1]);
            acc[2][0] = f2(x2, wv.x, acc[2][0]); acc[2][1] = f2(x2, wv.y, acc[2][1]);
            acc[3][0] = f2(x3, wv.x, acc[3][0]); acc[3][1] = f2(x3, wv.y, acc[3][1]);
        }
        #pragma unroll
        for (int i = 0; i < 4; i++) {
            ulonglong2 st; st.x = acc[i][0]; st.y = acc[i][1];
            *(ulonglong2*)(s_xp + (size_t)(ch * 128 + tg * 4 + i) * XP_STR + dg * 4) = st;
        }
    }
    __syncthreads();

    // ---------- phase 2: kkT = (xp@phi)^T ; q = (xp@alpha)/16 ----------
    float* sAl = s_A;                  // [64][16]
    float* sPh = s_A + 1024;           // [64][16]
    for (int i = tid; i < 1024; i += 512) { sAl[i] = alpha[i] * 0.0625f; sPh[i] = phi[i]; }
    __syncthreads();
    {
        const int w = tid >> 5, l = tid & 31;
        const int t2 = (w & 7) * 64 + l * 2 + (w >> 3);
        const bool doq = (w < 8);
        u64 kacc[8], qacc[8];
        #pragma unroll
        for (int j = 0; j < 8; j++) { kacc[j] = pk2(0.f, 0.f); qacc[j] = kacc[j]; }
        #pragma unroll 4
        for (int c4 = 0; c4 < 16; c4++) {
            float4 xv = *(const float4*)(s_xp + (size_t)t2 * XP_STR + c4 * 4);
            float xe[4] = {xv.x, xv.y, xv.z, xv.w};
            #pragma unroll
            for (int e = 0; e < 4; e++) {
                int c = c4 * 4 + e;
                u64 xd = pk2(xe[e], xe[e]);
                const ulonglong2* pp = (const ulonglong2*)(sPh + c * 16);
                ulonglong2 p0 = pp[0], p1 = pp[1], p2 = pp[2], p3 = pp[3];
                kacc[0] = f2(xd, p0.x, kacc[0]); kacc[1] = f2(xd, p0.y, kacc[1]);
                kacc[2] = f2(xd, p1.x, kacc[2]); kacc[3] = f2(xd, p1.y, kacc[3]);
                kacc[4] = f2(xd, p2.x, kacc[4]); kacc[5] = f2(xd, p2.y, kacc[5]);
                kacc[6] = f2(xd, p3.x, kacc[6]); kacc[7] = f2(xd, p3.y, kacc[7]);
                if (doq) {
                    const ulonglong2* aa = (const ulonglong2*)(sAl + c * 16);
                    ulonglong2 a0 = aa[0], a1 = aa[1], a2 = aa[2], a3 = aa[3];
                    qacc[0] = f2(xd, a0.x, qacc[0]); qacc[1] = f2(xd, a0.y, qacc[1]);
                    qacc[2] = f2(xd, a1.x, qacc[2]); qacc[3] = f2(xd, a1.y, qacc[3]);
                    qacc[4] = f2(xd, a2.x, qacc[4]); qacc[5] = f2(xd, a2.y, qacc[5]);
                    qacc[6] = f2(xd, a3.x, qacc[6]); qacc[7] = f2(xd, a3.y, qacc[7]);
                }
            }
        }
        #pragma unroll
        for (int j = 0; j < 8; j++) {
            float2 kv = up2(kacc[j]);
            s_kkT[(2 * j) * KKT_STR + t2]     = kv.x;
            s_kkT[(2 * j + 1) * KKT_STR + t2] = kv.y;
        }
        if (doq) {
            int s = t2 >> 1;
            u64* qrow = (u64*)(s_qa + s * 16);
            #pragma unroll
            for (int j = 0; j < 8; j++) qrow[j] = qacc[j];
        }
    }
    __syncthreads();

    // ---------- phase 3: 16 tiles of 16 s-rows ----------
    const int w = tid >> 5, l = tid & 31;
    const int rg = w & 3;              // scores: row group rg*4..+3
    const int qt = w >> 2;             // scores: t quarter
    const int rblk = (w & 1) * 8;      // gemm: s-rows rblk..+7
    const int dblk = (w >> 1) * 8;     // gemm: d cols dblk..+7
    float* s_att = s_A;                // [16][516]

    const float* kbase = s_kkT + qt * 128 + l * 4;
    const float* attb  = s_att + rblk * KKT_STR + l;
    const float* xpb   = s_xp + (size_t)l * XP_STR + dblk;
    const size_t dstg  = (size_t)SS * VV;

    for (int tile = 0; tile < 16; tile++) {
        const int s0 = tile * 16;

        // ---- scores: rows rg*4..+3, t = qt*128 + l*4 .. +3 ----
        u64 ac[4][2];
        #pragma unroll
        for (int r = 0; r < 4; r++) { ac[r][0] = pk2(0.f, 0.f); ac[r][1] = ac[r][0]; }
        #pragma unroll
        for (int j4 = 0; j4 < 4; j4++) {
            float4 q0 = *(const float4*)(s_qa + (s0 + rg * 4 + 0) * 16 + j4 * 4);
            float4 q1 = *(const float4*)(s_qa + (s0 + rg * 4 + 1) * 16 + j4 * 4);
            float4 q2 = *(const float4*)(s_qa + (s0 + rg * 4 + 2) * 16 + j4 * 4);
            float4 q3 = *(const float4*)(s_qa + (s0 + rg * 4 + 3) * 16 + j4 * 4);
            #pragma unroll
            for (int jj = 0; jj < 4; jj++) {
                ulonglong2 kv = *(const ulonglong2*)(kbase + (j4 * 4 + jj) * KKT_STR);
                float q0e = jj == 0 ? q0.x : jj == 1 ? q0.y : jj == 2 ? q0.z : q0.w;
                float q1e = jj == 0 ? q1.x : jj == 1 ? q1.y : jj == 2 ? q1.z : q1.w;
                float q2e = jj == 0 ? q2.x : jj == 1 ? q2.y : jj == 2 ? q2.z : q2.w;
                float q3e = jj == 0 ? q3.x : jj == 1 ? q3.y : jj == 2 ? q3.z : q3.w;
                u64 d0 = pk2(q0e, q0e), d1 = pk2(q1e, q1e);
                u64 d2 = pk2(q2e, q2e), d3 = pk2(q3e, q3e);
                ac[0][0] = f2(d0, kv.x, ac[0][0]); ac[0][1] = f2(d0, kv.y, ac[0][1]);
                ac[1][0] = f2(d1, kv.x, ac[1][0]); ac[1][1] = f2(d1, kv.y, ac[1][1]);
                ac[2][0] = f2(d2, kv.x, ac[2][0]); ac[2][1] = f2(d2, kv.y, ac[2][1]);
                ac[3][0] = f2(d3, kv.x, ac[3][0]); ac[3][1] = f2(d3, kv.y, ac[3][1]);
            }
        }

        // ---- exp (no max-sub: |score| << 1) + row sums ----
        float e[4][4];
        float rs[4];
        #pragma unroll
        for (int r = 0; r < 4; r++) {
            float2 lo = up2(ac[r][0]), hi = up2(ac[r][1]);
            e[r][0] = __expf(lo.x); e[r][1] = __expf(lo.y);
            e[r][2] = __expf(hi.x); e[r][3] = __expf(hi.y);
            rs[r] = (e[r][0] + e[r][1]) + (e[r][2] + e[r][3]);
            #pragma unroll
            for (int o = 16; o > 0; o >>= 1)
                rs[r] += __shfl_xor_sync(0xffffffffu, rs[r], o);
        }
        if (l == 0) {
            #pragma unroll
            for (int r = 0; r < 4; r++) s_red[(rg * 4 + r) * 4 + qt] = rs[r];
        }
        __syncthreads();                               // bar 1: sums ready

        // ---- normalize + band prior + store att ----
        #pragma unroll
        for (int r = 0; r < 4; r++) {
            int row = rg * 4 + r;
            float4 rv = *(const float4*)(s_red + row * 4);
            float inv = 1.0f / ((rv.x + rv.y) + (rv.z + rv.w));
            int tb = qt * 128 + l * 4;
            int tr = 2 * (s0 + row);
            float4 ev;
            ev.x = e[r][0] * inv; ev.y = e[r][1] * inv;
            ev.z = e[r][2] * inv; ev.w = e[r][3] * inv;
            int o;
            o = tb + 0 - tr + 4; if ((unsigned)o < 9u) ev.x += s_kb[o];
            o = tb + 1 - tr + 4; if ((unsigned)o < 9u) ev.y += s_kb[o];
            o = tb + 2 - tr + 4; if ((unsigned)o < 9u) ev.z += s_kb[o];
            o = tb + 3 - tr + 4; if ((unsigned)o < 9u) ev.w += s_kb[o];
            *(float4*)(s_att + row * KKT_STR + tb) = ev;
        }
        __syncthreads();                               // bar 2: att ready

        // ---- out GEMM: warp owns 8s x 8d block; lane = t-slice ----
        u64 A[32];                                     // m = r*4 + dpair
        #pragma unroll
        for (int m = 0; m < 32; m++) A[m] = pk2(0.f, 0.f);
        #pragma unroll 4
        for (int i = 0; i < 16; i++) {
            const float* xq = xpb + (size_t)(i * 32) * XP_STR;
            ulonglong2 xv0 = *(const ulonglong2*)(xq);
            ulonglong2 xv1 = *(const ulonglong2*)(xq + 4);
            const float* aq = attb + i * 32;
            #pragma unroll
            for (int r = 0; r < 8; r++) {
                float a = aq[r * KKT_STR];
                u64 ad = pk2(a, a);
                A[r*4+0] = f2(ad, xv0.x, A[r*4+0]);
                A[r*4+1] = f2(ad, xv0.y, A[r*4+1]);
                A[r*4+2] = f2(ad, xv1.x, A[r*4+2]);
                A[r*4+3] = f2(ad, xv1.y, A[r*4+3]);
            }
        }

        // ---- butterfly reduce: lane ends with element m = lane ----
        #pragma unroll
        for (int o = 16; o >= 1; o >>= 1) {
            bool hi = (l & o) != 0;
            #pragma unroll
            for (int j = 0; j < 16; j++) {
                if (j < o) {
                    u64 send = hi ? A[j] : A[j + o];
                    u64 keep = hi ? A[j + o] : A[j];
                    u64 got = __shfl_xor_sync(0xffffffffu, send, o);
                    A[j] = ad2(keep, got);
                }
            }
        }
        {
            float2 res = up2(A[0]);
            int r = l >> 2, dp = l & 3;
            int sidx = s0 + rblk + r;
            size_t ob = (((size_t)n * CC + dblk + dp * 2) * SS + sidx) * VV + v;
            out[ob] = res.x;
            out[ob + dstg] = res.y;
        }
        // no bar: next tile's att writes are ordered behind its own bar 1,
        // which this tile's GEMM reads precede in program order.
    }
}

extern "C" void kernel_launch(void* const* d_in, const int* in_sizes, int n_in,
                              void* d_out, int out_size)
{
    const float* x     = (const float*)d_in[0];
    const float* W     = (const float*)d_in[1];
    const float* alpha = (const float*)d_in[2];
    const float* phi   = (const float*)d_in[3];
    const float* karr  = (const float*)d_in[4];
    float* out = (float*)d_out;

    const int smemB = SMEM_FLOATS * sizeof(float);   // 222784 bytes
    cudaFuncSetAttribute(tgat5_kernel,
                         cudaFuncAttributeMaxDynamicSharedMemorySize, smemB);
    tgat5_kernel<<<NVB, 512, smemB>>>(x, W, alpha, phi, karr, out);
}

// round 11
// speedup vs baseline: 1.1203x; 1.1203x over previous
#include <cuda_runtime.h>

#define CC 64
#define TT 512
#define VV 25
#define DD 16
#define SS 256
#define NVB 400

#define XP_STR   68
#define KKT_BSTR 520                   // u16 stride for bf16 kkT rows
#define ATT_STR  516

#define OFF_XP   0
#define OFF_KKB  34816                 // float offset; 16*520 u16 = 4160 floats
#define OFF_QA   38976                 // [256][16] fp32 (= sW during phase 1)
#define OFF_A    43072                 // overlay, 8704 floats
#define OFF_KB   51776
#define OFF_RED  51792
#define SMEM_FLOATS 51856              // 207424 bytes

typedef unsigned long long u64;
typedef unsigned int u32;
typedef unsigned short u16;

__device__ float g_xT[(size_t)NVB * TT * CC];   // [n][v][t][c]  52.4 MB

__device__ __forceinline__ u64 pk2(float a, float b) {
    u64 r; asm("mov.b64 %0, {%1,%2};" : "=l"(r) : "f"(a), "f"(b)); return r;
}
__device__ __forceinline__ u64 f2(u64 a, u64 b, u64 c) {
    u64 d; asm("fma.rn.f32x2 %0, %1, %2, %3;" : "=l"(d) : "l"(a), "l"(b), "l"(c)); return d;
}
__device__ __forceinline__ u64 ad2(u64 a, u64 b) {
    u64 d; asm("add.rn.f32x2 %0, %1, %2;" : "=l"(d) : "l"(a), "l"(b)); return d;
}
__device__ __forceinline__ float2 up2(u64 a) {
    float lo, hi; asm("mov.b64 {%0,%1}, %2;" : "=f"(lo), "=f"(hi) : "l"(a));
    return make_float2(lo, hi);
}
__device__ __forceinline__ u16 f2bf(float a) {
    u16 h; asm("cvt.rn.bf16.f32 %0, %1;" : "=h"(h) : "f"(a)); return h;
}

// ---------------------------------------------------------------------------
// Transpose: x[n][c][t][v] -> g_xT[n][v][t][c]   (coalesced both sides)
// ---------------------------------------------------------------------------
__global__ void __launch_bounds__(256) xpose_kernel(const float* __restrict__ x)
{
    __shared__ float tile[32][33];
    const int n  = blockIdx.z;
    const int c0 = blockIdx.y * 32;
    const int j0 = blockIdx.x * 32;            // j = t*25 + v, 12800 total
    const int tx = threadIdx.x, ty = threadIdx.y;

    const float* xb = x + ((size_t)n * CC + c0) * (TT * VV) + j0;
    #pragma unroll
    for (int r = 0; r < 32; r += 8)
        tile[ty + r][tx] = xb[(size_t)(ty + r) * (TT * VV) + tx];
    __syncthreads();

    float* ob = g_xT + (size_t)n * VV * TT * CC;
    #pragma unroll
    for (int r = 0; r < 32; r += 8) {
        int j = j0 + ty + r;
        int t = j / VV, v = j - t * VV;
        ob[((size_t)v * TT + t) * CC + c0 + tx] = tile[tx][ty + r];
    }
}

// ---------------------------------------------------------------------------
// Fused main kernel
// ---------------------------------------------------------------------------
__global__ void __launch_bounds__(512, 1) tgat6_kernel(
    const float* __restrict__ W,
    const float* __restrict__ alpha, const float* __restrict__ phi,
    const float* __restrict__ karr, float* __restrict__ out)
{
    extern __shared__ float sm[];
    float* s_xp  = sm;                       // [512][68]
    u16*   s_kkb = (u16*)(sm + OFF_KKB);     // [16][520] bf16
    float* s_qa  = sm + OFF_QA;              // [256][16]  (= sW in phase 1)
    float* s_A   = sm + OFF_A;               // 8704-float overlay
    float* s_kb  = sm + OFF_KB;
    float* s_red = sm + OFF_RED;

    const int tid = threadIdx.x;
    const int nv = blockIdx.x;
    const int n = nv / VV, v = nv - n * VV;

    // ---------- phase 0: W -> smem (qa region), band kernel ----------
    float* sW = s_qa;
    for (int i = tid; i < CC * CC; i += 512) sW[i] = W[i];
    if (tid < 16) s_kb[tid] = (tid < 9) ? karr[tid] : 0.0f;

    // ---------- phase 1: xp = x^T W, 4 chunks of 128 t ----------
    // xT layout per (n,v): [t][c] contiguous. Coalesced LDG.128.
    const float* xTb = g_xT + (size_t)nv * TT * CC;
    float* xs = s_A;                         // [128 t][68]
    const int tl = tid >> 4;                 // 0..31  (t within 32-row group)
    const int c4 = tid & 15;                 // float4 column
    float4 g[4];
    #pragma unroll
    for (int k = 0; k < 4; k++)
        g[k] = *(const float4*)(xTb + ((size_t)(k * 32 + tl) * CC + c4 * 4));

    const int tg = tid >> 4, dg = tid & 15;
    for (int ch = 0; ch < 4; ch++) {
        if (ch > 0) __syncthreads();
        #pragma unroll
        for (int k = 0; k < 4; k++)
            *(float4*)(xs + (k * 32 + tl) * XP_STR + c4 * 4) = g[k];
        __syncthreads();
        if (ch < 3) {
            int tb = (ch + 1) * 128;
            #pragma unroll
            for (int k = 0; k < 4; k++)
                g[k] = *(const float4*)(xTb + ((size_t)(tb + k * 32 + tl) * CC + c4 * 4));
        }
        u64 acc[4][2];
        #pragma unroll
        for (int i = 0; i < 4; i++) { acc[i][0] = pk2(0.f, 0.f); acc[i][1] = acc[i][0]; }
        #pragma unroll 4
        for (int cq = 0; cq < 16; cq++) {
            float4 xq0 = *(const float4*)(xs + (tg * 4 + 0) * XP_STR + cq * 4);
            float4 xq1 = *(const float4*)(xs + (tg * 4 + 1) * XP_STR + cq * 4);
            float4 xq2 = *(const float4*)(xs + (tg * 4 + 2) * XP_STR + cq * 4);
            float4 xq3 = *(const float4*)(xs + (tg * 4 + 3) * XP_STR + cq * 4);
            #pragma unroll
            for (int e = 0; e < 4; e++) {
                ulonglong2 wv = *(const ulonglong2*)(sW + (cq * 4 + e) * 64 + dg * 4);
                float x0e = e == 0 ? xq0.x : e == 1 ? xq0.y : e == 2 ? xq0.z : xq0.w;
                float x1e = e == 0 ? xq1.x : e == 1 ? xq1.y : e == 2 ? xq1.z : xq1.w;
                float x2e = e == 0 ? xq2.x : e == 1 ? xq2.y : e == 2 ? xq2.z : xq2.w;
                float x3e = e == 0 ? xq3.x : e == 1 ? xq3.y : e == 2 ? xq3.z : xq3.w;
                u64 x0 = pk2(x0e, x0e), x1 = pk2(x1e, x1e);
                u64 x2 = pk2(x2e, x2e), x3 = pk2(x3e, x3e);
                acc[0][0] = f2(x0, wv.x, acc[0][0]); acc[0][1] = f2(x0, wv.y, acc[0][1]);
                acc[1][0] = f2(x1, wv.x, acc[1][0]); acc[1][1] = f2(x1, wv.y, acc[1][1]);
                acc[2][0] = f2(x2, wv.x, acc[2][0]); acc[2][1] = f2(x2, wv.y, acc[2][1]);
                acc[3][0] = f2(x3, wv.x, acc[3][0]); acc[3][1] = f2(x3, wv.y, acc[3][1]);
            }
        }
        #pragma unroll
        for (int i = 0; i < 4; i++) {
            ulonglong2 st; st.x = acc[i][0]; st.y = acc[i][1];
            *(ulonglong2*)(s_xp + (size_t)(ch * 128 + tg * 4 + i) * XP_STR + dg * 4) = st;
        }
    }
    __syncthreads();

    // ---------- phase 2: kkT(bf16) = (xp@phi)^T ; q = (xp@alpha)/16 ----------
    float* sAl = s_A;                  // [64][16]
    float* sPh = s_A + 1024;           // [64][16]
    for (int i = tid; i < 1024; i += 512) { sAl[i] = alpha[i] * 0.0625f; sPh[i] = phi[i]; }
    __syncthreads();
    {
        const int w = tid >> 5, l = tid & 31;
        const int t2 = (w & 7) * 64 + l * 2 + (w >> 3);
        const bool doq = (w < 8);
        u64 kacc[8], qacc[8];
        #pragma unroll
        for (int j = 0; j < 8; j++) { kacc[j] = pk2(0.f, 0.f); qacc[j] = kacc[j]; }
        #pragma unroll 4
        for (int cq = 0; cq < 16; cq++) {
            float4 xv = *(const float4*)(s_xp + (size_t)t2 * XP_STR + cq * 4);
            float xe[4] = {xv.x, xv.y, xv.z, xv.w};
            #pragma unroll
            for (int e = 0; e < 4; e++) {
                int c = cq * 4 + e;
                u64 xd = pk2(xe[e], xe[e]);
                const ulonglong2* pp = (const ulonglong2*)(sPh + c * 16);
                ulonglong2 p0 = pp[0], p1 = pp[1], p2 = pp[2], p3 = pp[3];
                kacc[0] = f2(xd, p0.x, kacc[0]); kacc[1] = f2(xd, p0.y, kacc[1]);
                kacc[2] = f2(xd, p1.x, kacc[2]); kacc[3] = f2(xd, p1.y, kacc[3]);
                kacc[4] = f2(xd, p2.x, kacc[4]); kacc[5] = f2(xd, p2.y, kacc[5]);
                kacc[6] = f2(xd, p3.x, kacc[6]); kacc[7] = f2(xd, p3.y, kacc[7]);
                if (doq) {
                    const ulonglong2* aa = (const ulonglong2*)(sAl + c * 16);
                    ulonglong2 a0 = aa[0], a1 = aa[1], a2 = aa[2], a3 = aa[3];
                    qacc[0] = f2(xd, a0.x, qacc[0]); qacc[1] = f2(xd, a0.y, qacc[1]);
                    qacc[2] = f2(xd, a1.x, qacc[2]); qacc[3] = f2(xd, a1.y, qacc[3]);
                    qacc[4] = f2(xd, a2.x, qacc[4]); qacc[5] = f2(xd, a2.y, qacc[5]);
                    qacc[6] = f2(xd, a3.x, qacc[6]); qacc[7] = f2(xd, a3.y, qacc[7]);
                }
            }
        }
        #pragma unroll
        for (int j = 0; j < 8; j++) {
            float2 kv = up2(kacc[j]);
            s_kkb[(2 * j) * KKT_BSTR + t2]     = f2bf(kv.x);
            s_kkb[(2 * j + 1) * KKT_BSTR + t2] = f2bf(kv.y);
        }
        if (doq) {
            int s = t2 >> 1;
            u64* qrow = (u64*)(s_qa + s * 16);
            #pragma unroll
            for (int j = 0; j < 8; j++) qrow[j] = qacc[j];
        }
    }
    __syncthreads();

    // ---------- phase 3: 16 tiles of 16 s-rows ----------
    const int w = tid >> 5, l = tid & 31;
    const int rg = w & 3;              // scores: row group rg*4..+3
    const int qt = w >> 2;             // scores: t quarter
    const int rblk = (w & 1) * 8;      // gemm: s-rows rblk..+7
    const int dblk = (w >> 1) * 8;     // gemm: d cols dblk..+7
    float* s_att = s_A;                // [16][516]

    const u16* kbb   = s_kkb + qt * 128 + l * 4;
    const float* attb = s_att + rblk * ATT_STR + l;
    const float* xpb  = s_xp + (size_t)l * XP_STR + dblk;
    const size_t dstg = (size_t)SS * VV;

    for (int tile = 0; tile < 16; tile++) {
        const int s0 = tile * 16;

        // ---- scores: rows rg*4..+3, t = qt*128 + l*4 .. +3 (kk bf16) ----
        u64 ac[4][2];
        #pragma unroll
        for (int r = 0; r < 4; r++) { ac[r][0] = pk2(0.f, 0.f); ac[r][1] = ac[r][0]; }
        #pragma unroll
        for (int j4 = 0; j4 < 4; j4++) {
            float4 q0 = *(const float4*)(s_qa + (s0 + rg * 4 + 0) * 16 + j4 * 4);
            float4 q1 = *(const float4*)(s_qa + (s0 + rg * 4 + 1) * 16 + j4 * 4);
            float4 q2 = *(const float4*)(s_qa + (s0 + rg * 4 + 2) * 16 + j4 * 4);
            float4 q3 = *(const float4*)(s_qa + (s0 + rg * 4 + 3) * 16 + j4 * 4);
            #pragma unroll
            for (int jj = 0; jj < 4; jj++) {
                u64 raw = *(const u64*)(kbb + (j4 * 4 + jj) * KKT_BSTR);
                u32 rlo = (u32)raw, rhi = (u32)(raw >> 32);
                u64 kx = ((u64)(rlo & 0xFFFF0000u) << 32) | (u64)(u32)(rlo << 16);
                u64 ky = ((u64)(rhi & 0xFFFF0000u) << 32) | (u64)(u32)(rhi << 16);
                float q0e = jj == 0 ? q0.x : jj == 1 ? q0.y : jj == 2 ? q0.z : q0.w;
                float q1e = jj == 0 ? q1.x : jj == 1 ? q1.y : jj == 2 ? q1.z : q1.w;
                float q2e = jj == 0 ? q2.x : jj == 1 ? q2.y : jj == 2 ? q2.z : q2.w;
                float q3e = jj == 0 ? q3.x : jj == 1 ? q3.y : jj == 2 ? q3.z : q3.w;
                u64 d0 = pk2(q0e, q0e), d1 = pk2(q1e, q1e);
                u64 d2 = pk2(q2e, q2e), d3 = pk2(q3e, q3e);
                ac[0][0] = f2(d0, kx, ac[0][0]); ac[0][1] = f2(d0, ky, ac[0][1]);
                ac[1][0] = f2(d1, kx, ac[1][0]); ac[1][1] = f2(d1, ky, ac[1][1]);
                ac[2][0] = f2(d2, kx, ac[2][0]); ac[2][1] = f2(d2, ky, ac[2][1]);
                ac[3][0] = f2(d3, kx, ac[3][0]); ac[3][1] = f2(d3, ky, ac[3][1]);
            }
        }

        // ---- exp (no max-sub: |score| << 1) + row sums ----
        float e[4][4];
        float rs[4];
        #pragma unroll
        for (int r = 0; r < 4; r++) {
            float2 lo = up2(ac[r][0]), hi = up2(ac[r][1]);
            e[r][0] = __expf(lo.x); e[r][1] = __expf(lo.y);
            e[r][2] = __expf(hi.x); e[r][3] = __expf(hi.y);
            rs[r] = (e[r][0] + e[r][1]) + (e[r][2] + e[r][3]);
            #pragma unroll
            for (int o = 16; o > 0; o >>= 1)
                rs[r] += __shfl_xor_sync(0xffffffffu, rs[r], o);
        }
        if (l == 0) {
            #pragma unroll
            for (int r = 0; r < 4; r++) s_red[(rg * 4 + r) * 4 + qt] = rs[r];
        }
        __syncthreads();                               // bar 1: sums ready

        // ---- normalize + band prior + store att ----
        #pragma unroll
        for (int r = 0; r < 4; r++) {
            int row = rg * 4 + r;
            float4 rv = *(const float4*)(s_red + row * 4);
            float inv = 1.0f / ((rv.x + rv.y) + (rv.z + rv.w));
            int tb = qt * 128 + l * 4;
            int tr = 2 * (s0 + row);
            float4 ev;
            ev.x = e[r][0] * inv; ev.y = e[r][1] * inv;
            ev.z = e[r][2] * inv; ev.w = e[r][3] * inv;
            int o;
            o = tb + 0 - tr + 4; if ((unsigned)o < 9u) ev.x += s_kb[o];
            o = tb + 1 - tr + 4; if ((unsigned)o < 9u) ev.y += s_kb[o];
            o = tb + 2 - tr + 4; if ((unsigned)o < 9u) ev.z += s_kb[o];
            o = tb + 3 - tr + 4; if ((unsigned)o < 9u) ev.w += s_kb[o];
            *(float4*)(s_att + row * ATT_STR + tb) = ev;
        }
        __syncthreads();                               // bar 2: att ready

        // ---- out GEMM: warp owns 8s x 8d block; lane = t-slice ----
        u64 A[32];
        #pragma unroll
        for (int m = 0; m < 32; m++) A[m] = pk2(0.f, 0.f);
        #pragma unroll 4
        for (int i = 0; i < 16; i++) {
            const float* xq = xpb + (size_t)(i * 32) * XP_STR;
            ulonglong2 xv0 = *(const ulonglong2*)(xq);
            ulonglong2 xv1 = *(const ulonglong2*)(xq + 4);
            const float* aq = attb + i * 32;
            #pragma unroll
            for (int r = 0; r < 8; r++) {
                float a = aq[r * ATT_STR];
                u64 ad = pk2(a, a);
                A[r*4+0] = f2(ad, xv0.x, A[r*4+0]);
                A[r*4+1] = f2(ad, xv0.y, A[r*4+1]);
                A[r*4+2] = f2(ad, xv1.x, A[r*4+2]);
                A[r*4+3] = f2(ad, xv1.y, A[r*4+3]);
            }
        }

        // ---- butterfly reduce: lane ends with element m = lane ----
        #pragma unroll
        for (int o = 16; o >= 1; o >>= 1) {
            bool hi = (l & o) != 0;
            #pragma unroll
            for (int j = 0; j < 16; j++) {
                if (j < o) {
                    u64 send = hi ? A[j] : A[j + o];
                    u64 keep = hi ? A[j + o] : A[j];
                    u64 got = __shfl_xor_sync(0xffffffffu, send, o);
                    A[j] = ad2(keep, got);
                }
            }
        }
        {
            float2 res = up2(A[0]);
            int r = l >> 2, dp = l & 3;
            int sidx = s0 + rblk + r;
            size_t ob = (((size_t)n * CC + dblk + dp * 2) * SS + sidx) * VV + v;
            out[ob] = res.x;
            out[ob + dstg] = res.y;
        }
        // no bar: next tile's att writes are ordered behind its own bar 1,
        // which this tile's GEMM reads precede in program order.
    }
}

extern "C" void kernel_launch(void* const* d_in, const int* in_sizes, int n_in,
                              void* d_out, int out_size)
{
    const float* x     = (const float*)d_in[0];
    const float* W     = (const float*)d_in[1];
    const float* alpha = (const float*)d_in[2];
    const float* phi   = (const float*)d_in[3];
    const float* karr  = (const float*)d_in[4];
    float* out = (float*)d_out;

    xpose_kernel<<<dim3(400, 2, 16), dim3(32, 8)>>>(x);

    const int smemB = SMEM_FLOATS * sizeof(float);   // 207424 bytes
    cudaFuncSetAttribute(tgat6_kernel,
                         cudaFuncAttributeMaxDynamicSharedMemorySize, smemB);
    tgat6_kernel<<<NVB, 512, smemB>>>(W, alpha, phi, karr, out);
}

// round 12
// speedup vs baseline: 1.3033x; 1.1634x over previous
#include <cuda_runtime.h>

#define CC 64
#define TT 512
#define VV 25
#define DD 16
#define SS 256
#define NVB 400

#define XS_STR   68
#define KKT_BSTR 520                   // u16 stride for bf16 kkT rows
#define ATT_STR  516

#define OFF_KKB  32768                 // float offsets
#define OFF_QA   36928
#define OFF_A    41024                 // overlay (xs / att), 8704 floats
#define OFF_D    49728                 // [4][16][68] partials
#define OFF_KB   54080
#define OFF_RED  54096
#define SMEM_FLOATS 54160              // 216640 bytes

typedef unsigned long long u64;
typedef unsigned int u32;
typedef unsigned short u16;

__device__ float g_xT[(size_t)NVB * TT * CC];   // [n][v][t][c]  52.4 MB

__device__ __forceinline__ u64 pk2(float a, float b) {
    u64 r; asm("mov.b64 %0, {%1,%2};" : "=l"(r) : "f"(a), "f"(b)); return r;
}
__device__ __forceinline__ u64 f2(u64 a, u64 b, u64 c) {
    u64 d; asm("fma.rn.f32x2 %0, %1, %2, %3;" : "=l"(d) : "l"(a), "l"(b), "l"(c)); return d;
}
__device__ __forceinline__ float2 up2(u64 a) {
    float lo, hi; asm("mov.b64 {%0,%1}, %2;" : "=f"(lo), "=f"(hi) : "l"(a));
    return make_float2(lo, hi);
}
__device__ __forceinline__ u16 f2bf(float a) {
    u16 h; asm("cvt.rn.bf16.f32 %0, %1;" : "=h"(h) : "f"(a)); return h;
}
__device__ __forceinline__ float tf32r(float a) {
    float r; asm("cvt.rna.tf32.f32 %0, %1;" : "=f"(r) : "f"(a)); return r;
}
__device__ __forceinline__ void mma8(float4& d, u32 a0, u32 a1, u32 a2, u32 a3,
                                     u32 b0, u32 b1) {
    asm("mma.sync.aligned.m16n8k8.row.col.f32.tf32.tf32.f32 "
        "{%0,%1,%2,%3},{%4,%5,%6,%7},{%8,%9},{%0,%1,%2,%3};"
        : "+f"(d.x), "+f"(d.y), "+f"(d.z), "+f"(d.w)
        : "r"(a0), "r"(a1), "r"(a2), "r"(a3), "r"(b0), "r"(b1));
}

// ---------------------------------------------------------------------------
// Transpose: x[n][c][t][v] -> g_xT[n][v][t][c]
// ---------------------------------------------------------------------------
__global__ void __launch_bounds__(256) xpose_kernel(const float* __restrict__ x)
{
    __shared__ float tile[32][33];
    const int n  = blockIdx.z;
    const int c0 = blockIdx.y * 32;
    const int j0 = blockIdx.x * 32;
    const int tx = threadIdx.x, ty = threadIdx.y;

    const float* xb = x + ((size_t)n * CC + c0) * (TT * VV) + j0;
    #pragma unroll
    for (int r = 0; r < 32; r += 8)
        tile[ty + r][tx] = xb[(size_t)(ty + r) * (TT * VV) + tx];
    __syncthreads();

    float* ob = g_xT + (size_t)n * VV * TT * CC;
    #pragma unroll
    for (int r = 0; r < 32; r += 8) {
        int j = j0 + ty + r;
        int t = j / VV, v = j - t * VV;
        ob[((size_t)v * TT + t) * CC + c0 + tx] = tile[tx][ty + r];
    }
}

// ---------------------------------------------------------------------------
// Fused main kernel
// ---------------------------------------------------------------------------
__global__ void __launch_bounds__(512, 1) tgat7_kernel(
    const float* __restrict__ W,
    const float* __restrict__ alpha, const float* __restrict__ phi,
    const float* __restrict__ karr, float* __restrict__ out)
{
    extern __shared__ float sm[];
    float* s_xp  = sm;                       // [512][64], col ^= 8*(t&3) swizzle
    u16*   s_kkb = (u16*)(sm + OFF_KKB);     // [16][520] bf16
    float* s_qa  = sm + OFF_QA;              // [256][16]  (= sW in phase 1)
    float* s_A   = sm + OFF_A;               // overlay: xs / att
    float* s_D   = sm + OFF_D;               // [4][16][68] mma partials
    float* s_kb  = sm + OFF_KB;
    float* s_red = sm + OFF_RED;

    const int tid = threadIdx.x;
    const int nv = blockIdx.x;
    const int n = nv / VV, v = nv - n * VV;

    // ---------- phase 0 ----------
    float* sW = s_qa;
    for (int i = tid; i < CC * CC; i += 512) sW[i] = W[i];
    if (tid < 16) s_kb[tid] = (tid < 9) ? karr[tid] : 0.0f;

    // ---------- phase 1: xp = x^T W (4 chunks of 128 t), swizzled store ----------
    const float* xTb = g_xT + (size_t)nv * TT * CC;
    float* xs = s_A;                         // [128][68]
    const int tl = tid >> 4;
    const int c4 = tid & 15;
    float4 g[4];
    #pragma unroll
    for (int k = 0; k < 4; k++)
        g[k] = *(const float4*)(xTb + ((size_t)(k * 32 + tl) * CC + c4 * 4));

    const int tg = tid >> 4, dg = tid & 15;
    for (int ch = 0; ch < 4; ch++) {
        if (ch > 0) __syncthreads();
        #pragma unroll
        for (int k = 0; k < 4; k++)
            *(float4*)(xs + (k * 32 + tl) * XS_STR + c4 * 4) = g[k];
        __syncthreads();
        if (ch < 3) {
            int tb = (ch + 1) * 128;
            #pragma unroll
            for (int k = 0; k < 4; k++)
                g[k] = *(const float4*)(xTb + ((size_t)(tb + k * 32 + tl) * CC + c4 * 4));
        }
        u64 acc[4][2];
        #pragma unroll
        for (int i = 0; i < 4; i++) { acc[i][0] = pk2(0.f, 0.f); acc[i][1] = acc[i][0]; }
        #pragma unroll 4
        for (int cq = 0; cq < 16; cq++) {
            float4 xq0 = *(const float4*)(xs + (tg * 4 + 0) * XS_STR + cq * 4);
            float4 xq1 = *(const float4*)(xs + (tg * 4 + 1) * XS_STR + cq * 4);
            float4 xq2 = *(const float4*)(xs + (tg * 4 + 2) * XS_STR + cq * 4);
            float4 xq3 = *(const float4*)(xs + (tg * 4 + 3) * XS_STR + cq * 4);
            #pragma unroll
            for (int e = 0; e < 4; e++) {
                ulonglong2 wv = *(const ulonglong2*)(sW + (cq * 4 + e) * 64 + dg * 4);
                float x0e = e == 0 ? xq0.x : e == 1 ? xq0.y : e == 2 ? xq0.z : xq0.w;
                float x1e = e == 0 ? xq1.x : e == 1 ? xq1.y : e == 2 ? xq1.z : xq1.w;
                float x2e = e == 0 ? xq2.x : e == 1 ? xq2.y : e == 2 ? xq2.z : xq2.w;
                float x3e = e == 0 ? xq3.x : e == 1 ? xq3.y : e == 2 ? xq3.z : xq3.w;
                u64 x0 = pk2(x0e, x0e), x1 = pk2(x1e, x1e);
                u64 x2 = pk2(x2e, x2e), x3 = pk2(x3e, x3e);
                acc[0][0] = f2(x0, wv.x, acc[0][0]); acc[0][1] = f2(x0, wv.y, acc[0][1]);
                acc[1][0] = f2(x1, wv.x, acc[1][0]); acc[1][1] = f2(x1, wv.y, acc[1][1]);
                acc[2][0] = f2(x2, wv.x, acc[2][0]); acc[2][1] = f2(x2, wv.y, acc[2][1]);
                acc[3][0] = f2(x3, wv.x, acc[3][0]); acc[3][1] = f2(x3, wv.y, acc[3][1]);
            }
        }
        #pragma unroll
        for (int i = 0; i < 4; i++) {
            int colw = (dg * 4) ^ (8 * (i & 3));     // t&3 == i here
            ulonglong2 st; st.x = acc[i][0]; st.y = acc[i][1];
            *(ulonglong2*)(s_xp + (size_t)(ch * 128 + tg * 4 + i) * 64 + colw) = st;
        }
    }
    __syncthreads();

    // ---------- phase 2: kkT(bf16) = (xp@phi)^T ; q = (xp@alpha)/16 ----------
    float* sAl = s_A;
    float* sPh = s_A + 1024;
    for (int i = tid; i < 1024; i += 512) { sAl[i] = alpha[i] * 0.0625f; sPh[i] = phi[i]; }
    __syncthreads();
    {
        const int w = tid >> 5, l = tid & 31;
        const int t2 = (w & 7) * 64 + l * 2 + (w >> 3);
        const bool doq = (w < 8);
        const int x3 = 8 * (t2 & 3);
        u64 kacc[8], qacc[8];
        #pragma unroll
        for (int j = 0; j < 8; j++) { kacc[j] = pk2(0.f, 0.f); qacc[j] = kacc[j]; }
        #pragma unroll 4
        for (int cq = 0; cq < 16; cq++) {
            float4 xv = *(const float4*)(s_xp + (size_t)t2 * 64 + ((cq * 4) ^ x3));
            float xe[4] = {xv.x, xv.y, xv.z, xv.w};
            #pragma unroll
            for (int e = 0; e < 4; e++) {
                int c = cq * 4 + e;
                u64 xd = pk2(xe[e], xe[e]);
                const ulonglong2* pp = (const ulonglong2*)(sPh + c * 16);
                ulonglong2 p0 = pp[0], p1 = pp[1], p2 = pp[2], p3 = pp[3];
                kacc[0] = f2(xd, p0.x, kacc[0]); kacc[1] = f2(xd, p0.y, kacc[1]);
                kacc[2] = f2(xd, p1.x, kacc[2]); kacc[3] = f2(xd, p1.y, kacc[3]);
                kacc[4] = f2(xd, p2.x, kacc[4]); kacc[5] = f2(xd, p2.y, kacc[5]);
                kacc[6] = f2(xd, p3.x, kacc[6]); kacc[7] = f2(xd, p3.y, kacc[7]);
                if (doq) {
                    const ulonglong2* aa = (const ulonglong2*)(sAl + c * 16);
                    ulonglong2 a0 = aa[0], a1 = aa[1], a2 = aa[2], a3 = aa[3];
                    qacc[0] = f2(xd, a0.x, qacc[0]); qacc[1] = f2(xd, a0.y, qacc[1]);
                    qacc[2] = f2(xd, a1.x, qacc[2]); qacc[3] = f2(xd, a1.y, qacc[3]);
                    qacc[4] = f2(xd, a2.x, qacc[4]); qacc[5] = f2(xd, a2.y, qacc[5]);
                    qacc[6] = f2(xd, a3.x, qacc[6]); qacc[7] = f2(xd, a3.y, qacc[7]);
                }
            }
        }
        #pragma unroll
        for (int j = 0; j < 8; j++) {
            float2 kv = up2(kacc[j]);
            s_kkb[(2 * j) * KKT_BSTR + t2]     = f2bf(kv.x);
            s_kkb[(2 * j + 1) * KKT_BSTR + t2] = f2bf(kv.y);
        }
        if (doq) {
            int s = t2 >> 1;
            u64* qrow = (u64*)(s_qa + s * 16);
            #pragma unroll
            for (int j = 0; j < 8; j++) qrow[j] = qacc[j];
        }
    }
    __syncthreads();

    // ---------- phase 2.5: round xp to tf32 in place ----------
    #pragma unroll
    for (int kx = 0; kx < 16; kx++) {
        int idx = tid + kx * 512;           // float4 index
        int row = idx >> 4, cq = idx & 15;
        float* p = s_xp + (size_t)row * 64 + ((cq * 4) ^ (8 * (row & 3)));
        float4 vv = *(const float4*)p;
        vv.x = tf32r(vv.x); vv.y = tf32r(vv.y);
        vv.z = tf32r(vv.z); vv.w = tf32r(vv.w);
        *(float4*)p = vv;
    }
    __syncthreads();

    // ---------- phase 3: 16 tiles of 16 s-rows ----------
    const int w = tid >> 5, l = tid & 31;
    const int rg = w & 3;              // scores: row group rg*4..+3
    const int qt = w >> 2;             // scores: t quarter
    const int tq = w & 3;              // gemm: t quarter (K=128)
    const int ds = w >> 2;             // gemm: d slice (16 cols)
    float* s_att = s_A;                // [16][516]

    const u16* kbb = s_kkb + qt * 128 + l * 4;
    const float* aP = s_att + (l >> 2) * ATT_STR + (l & 3) + tq * 128;
    const int cb0 = (ds * 16 + (l >> 2)) ^ (8 * (l & 3));
    const int cb1 = (ds * 16 + 8 + (l >> 2)) ^ (8 * (l & 3));
    const float* bB = s_xp + (size_t)(tq * 128 + (l & 3)) * 64;
    const size_t dstg = (size_t)SS * VV;

    for (int tile = 0; tile < 16; tile++) {
        const int s0 = tile * 16;

        // ---- scores: rows rg*4..+3, t = qt*128 + l*4 .. +3 (kk bf16) ----
        u64 ac[4][2];
        #pragma unroll
        for (int r = 0; r < 4; r++) { ac[r][0] = pk2(0.f, 0.f); ac[r][1] = ac[r][0]; }
        #pragma unroll
        for (int j4 = 0; j4 < 4; j4++) {
            float4 q0 = *(const float4*)(s_qa + (s0 + rg * 4 + 0) * 16 + j4 * 4);
            float4 q1 = *(const float4*)(s_qa + (s0 + rg * 4 + 1) * 16 + j4 * 4);
            float4 q2 = *(const float4*)(s_qa + (s0 + rg * 4 + 2) * 16 + j4 * 4);
            float4 q3 = *(const float4*)(s_qa + (s0 + rg * 4 + 3) * 16 + j4 * 4);
            #pragma unroll
            for (int jj = 0; jj < 4; jj++) {
                u64 raw = *(const u64*)(kbb + (j4 * 4 + jj) * KKT_BSTR);
                u32 rlo = (u32)raw, rhi = (u32)(raw >> 32);
                u64 kx = ((u64)(rlo & 0xFFFF0000u) << 32) | (u64)(u32)(rlo << 16);
                u64 ky = ((u64)(rhi & 0xFFFF0000u) << 32) | (u64)(u32)(rhi << 16);
                float q0e = jj == 0 ? q0.x : jj == 1 ? q0.y : jj == 2 ? q0.z : q0.w;
                float q1e = jj == 0 ? q1.x : jj == 1 ? q1.y : jj == 2 ? q1.z : q1.w;
                float q2e = jj == 0 ? q2.x : jj == 1 ? q2.y : jj == 2 ? q2.z : q2.w;
                float q3e = jj == 0 ? q3.x : jj == 1 ? q3.y : jj == 2 ? q3.z : q3.w;
                u64 d0 = pk2(q0e, q0e), d1 = pk2(q1e, q1e);
                u64 d2 = pk2(q2e, q2e), d3 = pk2(q3e, q3e);
                ac[0][0] = f2(d0, kx, ac[0][0]); ac[0][1] = f2(d0, ky, ac[0][1]);
                ac[1][0] = f2(d1, kx, ac[1][0]); ac[1][1] = f2(d1, ky, ac[1][1]);
                ac[2][0] = f2(d2, kx, ac[2][0]); ac[2][1] = f2(d2, ky, ac[2][1]);
                ac[3][0] = f2(d3, kx, ac[3][0]); ac[3][1] = f2(d3, ky, ac[3][1]);
            }
        }

        // ---- exp + row sums ----
        float e[4][4];
        float rs[4];
        #pragma unroll
        for (int r = 0; r < 4; r++) {
            float2 lo = up2(ac[r][0]), hi = up2(ac[r][1]);
            e[r][0] = __expf(lo.x); e[r][1] = __expf(lo.y);
            e[r][2] = __expf(hi.x); e[r][3] = __expf(hi.y);
            rs[r] = (e[r][0] + e[r][1]) + (e[r][2] + e[r][3]);
            #pragma unroll
            for (int o = 16; o > 0; o >>= 1)
                rs[r] += __shfl_xor_sync(0xffffffffu, rs[r], o);
        }
        if (l == 0) {
            #pragma unroll
            for (int r = 0; r < 4; r++) s_red[(rg * 4 + r) * 4 + qt] = rs[r];
        }
        __syncthreads();                               // bar 1

        // ---- normalize + band prior + store att (tf32-rounded) ----
        #pragma unroll
        for (int r = 0; r < 4; r++) {
            int row = rg * 4 + r;
            float4 rv = *(const float4*)(s_red + row * 4);
            float inv = 1.0f / ((rv.x + rv.y) + (rv.z + rv.w));
            int tb = qt * 128 + l * 4;
            int tr = 2 * (s0 + row);
            float4 ev;
            ev.x = e[r][0] * inv; ev.y = e[r][1] * inv;
            ev.z = e[r][2] * inv; ev.w = e[r][3] * inv;
            int o;
            o = tb + 0 - tr + 4; if ((unsigned)o < 9u) ev.x += s_kb[o];
            o = tb + 1 - tr + 4; if ((unsigned)o < 9u) ev.y += s_kb[o];
            o = tb + 2 - tr + 4; if ((unsigned)o < 9u) ev.z += s_kb[o];
            o = tb + 3 - tr + 4; if ((unsigned)o < 9u) ev.w += s_kb[o];
            ev.x = tf32r(ev.x); ev.y = tf32r(ev.y);
            ev.z = tf32r(ev.z); ev.w = tf32r(ev.w);
            *(float4*)(s_att + row * ATT_STR + tb) = ev;
        }
        __syncthreads();                               // bar 2

        // ---- out GEMM via tf32 mma: warp = (tq, ds) ----
        float4 D0 = make_float4(0.f, 0.f, 0.f, 0.f);
        float4 D1 = make_float4(0.f, 0.f, 0.f, 0.f);
        #pragma unroll 4
        for (int kc = 0; kc < 16; kc++) {
            const float* ak = aP + kc * 8;
            u32 a0 = __float_as_uint(ak[0]);
            u32 a1 = __float_as_uint(ak[8 * ATT_STR]);
            u32 a2 = __float_as_uint(ak[4]);
            u32 a3 = __float_as_uint(ak[4 + 8 * ATT_STR]);
            const float* bk = bB + kc * 512;
            u32 b00 = __float_as_uint(bk[cb0]);
            u32 b01 = __float_as_uint(bk[256 + cb0]);
            u32 b10 = __float_as_uint(bk[cb1]);
            u32 b11 = __float_as_uint(bk[256 + cb1]);
            mma8(D0, a0, a1, a2, a3, b00, b01);
            mma8(D1, a0, a1, a2, a3, b10, b11);
        }
        {
            int r = l >> 2, c2 = 2 * (l & 3);
            float* dp = s_D + tq * 1088 + r * 68 + ds * 16;
            *(float2*)(dp + c2)            = make_float2(D0.x, D0.y);
            *(float2*)(dp + c2 + 8 * 68)   = make_float2(D0.z, D0.w);
            *(float2*)(dp + c2 + 8)        = make_float2(D1.x, D1.y);
            *(float2*)(dp + c2 + 8 + 8 * 68) = make_float2(D1.z, D1.w);
        }
        __syncthreads();                               // bar 3

        // ---- reduce 4 t-quarter partials + store to gmem ----
        {
            int srow = tid >> 5, dloc = (tid & 31) * 2;
            const float* pD = s_D + srow * 68 + dloc;
            float2 p0 = *(const float2*)(pD);
            float2 p1 = *(const float2*)(pD + 1088);
            float2 p2 = *(const float2*)(pD + 2176);
            float2 p3 = *(const float2*)(pD + 3264);
            float ox = (p0.x + p1.x) + (p2.x + p3.x);
            float oy = (p0.y + p1.y) + (p2.y + p3.y);
            int sidx = s0 + srow;
            size_t ob = (((size_t)n * CC + dloc) * SS + sidx) * VV + v;
            out[ob] = ox;
            out[ob + dstg] = oy;
        }
        // no bar: next tile's att writes are behind its bar 1; next tile's
        // s_D writes are behind its bar 2 — both after every thread's reads here.
    }
}

extern "C" void kernel_launch(void* const* d_in, const int* in_sizes, int n_in,
                              void* d_out, int out_size)
{
    const float* x     = (const float*)d_in[0];
    const float* W     = (const float*)d_in[1];
    const float* alpha = (const float*)d_in[2];
    const float* phi   = (const float*)d_in[3];
    const float* karr  = (const float*)d_in[4];
    float* out = (float*)d_out;

    xpose_kernel<<<dim3(400, 2, 16), dim3(32, 8)>>>(x);

    const int smemB = SMEM_FLOATS * sizeof(float);   // 216640 bytes
    cudaFuncSetAttribute(tgat7_kernel,
                         cudaFuncAttributeMaxDynamicSharedMemorySize, smemB);
    tgat7_kernel<<<NVB, 512, smemB>>>(W, alpha, phi, karr, out);
}

// round 13
// speedup vs baseline: 1.4462x; 1.1096x over previous
#include <cuda_runtime.h>

#define CC 64
#define TT 512
#define VV 25
#define DD 16
#define SS 256
#define NVB 400

#define XS_STR   68
#define ATT_STR  516
#define QB_STR   24                    // u16 stride for bf16 q rows
#define KK_STR   24                    // u16 stride for bf16 kk rows ([t][j])
#define D_STR    66
#define D_Q      1056                  // 16*66

#define OFF_KKB  32768                 // float offsets; u16[512][24] = 6144 floats
#define OFF_QB   38912                 // region 4096 floats: sW in phase1, qb bf16 later
#define OFF_A    43008                 // overlay (xs [128][68] | att [16][516]), 8704
#define OFF_D    51712                 // [4][16][66] = 4224
#define OFF_RED  55936                 // [2][16][16] = 512
#define OFF_KB   56448                 // 16
#define SMEM_FLOATS 56464              // 225856 bytes

typedef unsigned long long u64;
typedef unsigned int u32;
typedef unsigned short u16;

__device__ float g_xT[(size_t)NVB * TT * CC];   // [n][v][t][c]  52.4 MB

__device__ __forceinline__ u64 pk2(float a, float b) {
    u64 r; asm("mov.b64 %0, {%1,%2};" : "=l"(r) : "f"(a), "f"(b)); return r;
}
__device__ __forceinline__ u64 f2(u64 a, u64 b, u64 c) {
    u64 d; asm("fma.rn.f32x2 %0, %1, %2, %3;" : "=l"(d) : "l"(a), "l"(b), "l"(c)); return d;
}
__device__ __forceinline__ float2 up2(u64 a) {
    float lo, hi; asm("mov.b64 {%0,%1}, %2;" : "=f"(lo), "=f"(hi) : "l"(a));
    return make_float2(lo, hi);
}
__device__ __forceinline__ u16 f2bf(float a) {
    u16 h; asm("cvt.rn.bf16.f32 %0, %1;" : "=h"(h) : "f"(a)); return h;
}
__device__ __forceinline__ u32 pkbf(u64 p) {
    float2 f = up2(p);
    return (u32)f2bf(f.x) | ((u32)f2bf(f.y) << 16);
}
__device__ __forceinline__ float tf32r(float a) {
    float r; asm("cvt.rna.tf32.f32 %0, %1;" : "=f"(r) : "f"(a)); return r;
}
__device__ __forceinline__ void mma8(float4& d, u32 a0, u32 a1, u32 a2, u32 a3,
                                     u32 b0, u32 b1) {
    asm("mma.sync.aligned.m16n8k8.row.col.f32.tf32.tf32.f32 "
        "{%0,%1,%2,%3},{%4,%5,%6,%7},{%8,%9},{%0,%1,%2,%3};"
        : "+f"(d.x), "+f"(d.y), "+f"(d.z), "+f"(d.w)
        : "r"(a0), "r"(a1), "r"(a2), "r"(a3), "r"(b0), "r"(b1));
}
__device__ __forceinline__ void mma16bf(float4& d, u32 a0, u32 a1, u32 a2, u32 a3,
                                        u32 b0, u32 b1) {
    asm("mma.sync.aligned.m16n8k16.row.col.f32.bf16.bf16.f32 "
        "{%0,%1,%2,%3},{%4,%5,%6,%7},{%8,%9},{%0,%1,%2,%3};"
        : "+f"(d.x), "+f"(d.y), "+f"(d.z), "+f"(d.w)
        : "r"(a0), "r"(a1), "r"(a2), "r"(a3), "r"(b0), "r"(b1));
}

// ---------------------------------------------------------------------------
// Transpose: x[n][c][t][v] -> g_xT[n][v][t][c]
// ---------------------------------------------------------------------------
__global__ void __launch_bounds__(256) xpose_kernel(const float* __restrict__ x)
{
    __shared__ float tile[32][33];
    const int n  = blockIdx.z;
    const int c0 = blockIdx.y * 32;
    const int j0 = blockIdx.x * 32;
    const int tx = threadIdx.x, ty = threadIdx.y;

    const float* xb = x + ((size_t)n * CC + c0) * (TT * VV) + j0;
    #pragma unroll
    for (int r = 0; r < 32; r += 8)
        tile[ty + r][tx] = xb[(size_t)(ty + r) * (TT * VV) + tx];
    __syncthreads();

    float* ob = g_xT + (size_t)n * VV * TT * CC;
    #pragma unroll
    for (int r = 0; r < 32; r += 8) {
        int j = j0 + ty + r;
        int t = j / VV, v = j - t * VV;
        ob[((size_t)v * TT + t) * CC + c0 + tx] = tile[tx][ty + r];
    }
}

// ---------------------------------------------------------------------------
// Fused main kernel
// ---------------------------------------------------------------------------
__global__ void __launch_bounds__(512, 1) tgat8_kernel(
    const float* __restrict__ W,
    const float* __restrict__ alpha, const float* __restrict__ phi,
    const float* __restrict__ karr, float* __restrict__ out)
{
    extern __shared__ float sm[];
    float* s_xp  = sm;                       // [512][64], col ^= 8*(t&3) swizzle
    u16*   s_kk2 = (u16*)(sm + OFF_KKB);     // [512][24] bf16 (kkT as [t][j])
    u16*   s_qb  = (u16*)(sm + OFF_QB);      // [256][24] bf16 (after phase 2)
    float* s_A   = sm + OFF_A;               // overlay: xs / att
    float* s_D   = sm + OFF_D;               // [4][16][66]
    float* s_red = sm + OFF_RED;             // [2][16][16]
    float* s_kb  = sm + OFF_KB;

    const int tid = threadIdx.x;
    const int nv = blockIdx.x;
    const int n = nv / VV, v = nv - n * VV;

    // ---------- phase 0 ----------
    float* sW = sm + OFF_QB;                 // W staged in qb region for phase 1
    for (int i = tid; i < CC * CC; i += 512) sW[i] = W[i];
    if (tid < 16) s_kb[tid] = (tid < 9) ? karr[tid] : 0.0f;

    // ---------- phase 1: xp = x^T W (4 chunks of 128 t), swizzled store ----------
    const float* xTb = g_xT + (size_t)nv * TT * CC;
    float* xs = s_A;                         // [128][68]
    const int tl = tid >> 4;
    const int c4 = tid & 15;
    float4 g[4];
    #pragma unroll
    for (int k = 0; k < 4; k++)
        g[k] = *(const float4*)(xTb + ((size_t)(k * 32 + tl) * CC + c4 * 4));

    const int tg = tid >> 4, dg = tid & 15;
    for (int ch = 0; ch < 4; ch++) {
        if (ch > 0) __syncthreads();
        #pragma unroll
        for (int k = 0; k < 4; k++)
            *(float4*)(xs + (k * 32 + tl) * XS_STR + c4 * 4) = g[k];
        __syncthreads();
        if (ch < 3) {
            int tb = (ch + 1) * 128;
            #pragma unroll
            for (int k = 0; k < 4; k++)
                g[k] = *(const float4*)(xTb + ((size_t)(tb + k * 32 + tl) * CC + c4 * 4));
        }
        u64 acc[4][2];
        #pragma unroll
        for (int i = 0; i < 4; i++) { acc[i][0] = pk2(0.f, 0.f); acc[i][1] = acc[i][0]; }
        #pragma unroll 4
        for (int cq = 0; cq < 16; cq++) {
            float4 xq0 = *(const float4*)(xs + (tg * 4 + 0) * XS_STR + cq * 4);
            float4 xq1 = *(const float4*)(xs + (tg * 4 + 1) * XS_STR + cq * 4);
            float4 xq2 = *(const float4*)(xs + (tg * 4 + 2) * XS_STR + cq * 4);
            float4 xq3 = *(const float4*)(xs + (tg * 4 + 3) * XS_STR + cq * 4);
            #pragma unroll
            for (int e = 0; e < 4; e++) {
                ulonglong2 wv = *(const ulonglong2*)(sW + (cq * 4 + e) * 64 + dg * 4);
                float x0e = e == 0 ? xq0.x : e == 1 ? xq0.y : e == 2 ? xq0.z : xq0.w;
                float x1e = e == 0 ? xq1.x : e == 1 ? xq1.y : e == 2 ? xq1.z : xq1.w;
                float x2e = e == 0 ? xq2.x : e == 1 ? xq2.y : e == 2 ? xq2.z : xq2.w;
                float x3e = e == 0 ? xq3.x : e == 1 ? xq3.y : e == 2 ? xq3.z : xq3.w;
                u64 x0 = pk2(x0e, x0e), x1 = pk2(x1e, x1e);
                u64 x2 = pk2(x2e, x2e), x3 = pk2(x3e, x3e);
                acc[0][0] = f2(x0, wv.x, acc[0][0]); acc[0][1] = f2(x0, wv.y, acc[0][1]);
                acc[1][0] = f2(x1, wv.x, acc[1][0]); acc[1][1] = f2(x1, wv.y, acc[1][1]);
                acc[2][0] = f2(x2, wv.x, acc[2][0]); acc[2][1] = f2(x2, wv.y, acc[2][1]);
                acc[3][0] = f2(x3, wv.x, acc[3][0]); acc[3][1] = f2(x3, wv.y, acc[3][1]);
            }
        }
        #pragma unroll
        for (int i = 0; i < 4; i++) {
            int colw = (dg * 4) ^ (8 * (i & 3));     // t&3 == i here
            ulonglong2 st; st.x = acc[i][0]; st.y = acc[i][1];
            *(ulonglong2*)(s_xp + (size_t)(ch * 128 + tg * 4 + i) * 64 + colw) = st;
        }
    }
    __syncthreads();

    // ---------- phase 2: kk2(bf16,[t][j]) = xp@phi ; qb(bf16) = (xp@alpha)/16 ----------
    float* sAl = s_A;
    float* sPh = s_A + 1024;
    for (int i = tid; i < 1024; i += 512) { sAl[i] = alpha[i] * 0.0625f; sPh[i] = phi[i]; }
    __syncthreads();
    {
        const int w = tid >> 5, l = tid & 31;
        const int t2 = (w & 7) * 64 + l * 2 + (w >> 3);
        const bool doq = (w < 8);
        const int x3 = 8 * (t2 & 3);
        u64 kacc[8], qacc[8];
        #pragma unroll
        for (int j = 0; j < 8; j++) { kacc[j] = pk2(0.f, 0.f); qacc[j] = kacc[j]; }
        #pragma unroll 4
        for (int cq = 0; cq < 16; cq++) {
            float4 xv = *(const float4*)(s_xp + (size_t)t2 * 64 + ((cq * 4) ^ x3));
            float xe[4] = {xv.x, xv.y, xv.z, xv.w};
            #pragma unroll
            for (int e = 0; e < 4; e++) {
                int c = cq * 4 + e;
                u64 xd = pk2(xe[e], xe[e]);
                const ulonglong2* pp = (const ulonglong2*)(sPh + c * 16);
                ulonglong2 p0 = pp[0], p1 = pp[1], p2 = pp[2], p3 = pp[3];
                kacc[0] = f2(xd, p0.x, kacc[0]); kacc[1] = f2(xd, p0.y, kacc[1]);
                kacc[2] = f2(xd, p1.x, kacc[2]); kacc[3] = f2(xd, p1.y, kacc[3]);
                kacc[4] = f2(xd, p2.x, kacc[4]); kacc[5] = f2(xd, p2.y, kacc[5]);
                kacc[6] = f2(xd, p3.x, kacc[6]); kacc[7] = f2(xd, p3.y, kacc[7]);
                if (doq) {
                    const ulonglong2* aa = (const ulonglong2*)(sAl + c * 16);
                    ulonglong2 a0 = aa[0], a1 = aa[1], a2 = aa[2], a3 = aa[3];
                    qacc[0] = f2(xd, a0.x, qacc[0]); qacc[1] = f2(xd, a0.y, qacc[1]);
                    qacc[2] = f2(xd, a1.x, qacc[2]); qacc[3] = f2(xd, a1.y, qacc[3]);
                    qacc[4] = f2(xd, a2.x, qacc[4]); qacc[5] = f2(xd, a2.y, qacc[5]);
                    qacc[6] = f2(xd, a3.x, qacc[6]); qacc[7] = f2(xd, a3.y, qacc[7]);
                }
            }
        }
        uint4 kv0, kv1;
        kv0.x = pkbf(kacc[0]); kv0.y = pkbf(kacc[1]);
        kv0.z = pkbf(kacc[2]); kv0.w = pkbf(kacc[3]);
        kv1.x = pkbf(kacc[4]); kv1.y = pkbf(kacc[5]);
        kv1.z = pkbf(kacc[6]); kv1.w = pkbf(kacc[7]);
        *(uint4*)(s_kk2 + (size_t)t2 * KK_STR)     = kv0;
        *(uint4*)(s_kk2 + (size_t)t2 * KK_STR + 8) = kv1;
        if (doq) {
            int s = t2 >> 1;
            uint4 q0, q1;
            q0.x = pkbf(qacc[0]); q0.y = pkbf(qacc[1]);
            q0.z = pkbf(qacc[2]); q0.w = pkbf(qacc[3]);
            q1.x = pkbf(qacc[4]); q1.y = pkbf(qacc[5]);
            q1.z = pkbf(qacc[6]); q1.w = pkbf(qacc[7]);
            *(uint4*)(s_qb + (size_t)s * QB_STR)     = q0;
            *(uint4*)(s_qb + (size_t)s * QB_STR + 8) = q1;
        }
    }
    __syncthreads();

    // ---------- phase 2.5: round xp to tf32 in place ----------
    #pragma unroll
    for (int kx = 0; kx < 16; kx++) {
        int idx = tid + kx * 512;
        int row = idx >> 4, cq = idx & 15;
        float* p = s_xp + (size_t)row * 64 + ((cq * 4) ^ (8 * (row & 3)));
        float4 vv = *(const float4*)p;
        vv.x = tf32r(vv.x); vv.y = tf32r(vv.y);
        vv.z = tf32r(vv.z); vv.w = tf32r(vv.w);
        *(float4*)p = vv;
    }
    __syncthreads();

    // ---------- phase 3: 16 tiles of 16 s-rows ----------
    const int w = tid >> 5, l = tid & 31;
    const int r4 = l >> 2, cl = l & 3;
    const int tq = w & 3;              // gemm: t quarter
    const int ds = w >> 2;             // gemm: d slice (16 cols)
    float* s_att = s_A;                // [16][516]

    const float* aP = s_att + r4 * ATT_STR + cl + tq * 128;
    const int cb0 = (ds * 16 + r4) ^ (8 * cl);
    const int cb1 = (ds * 16 + 8 + r4) ^ (8 * cl);
    const float* bB = s_xp + (size_t)(tq * 128 + cl) * 64;
    const size_t dstg = (size_t)SS * VV;
    const int srow = tid >> 5, dloc = (tid & 31) * 2;

    for (int tile = 0; tile < 16; tile++) {
        const int s0 = tile * 16;
        float* redp = s_red + (tile & 1) * 256;

        // ---- scores via bf16 mma: warp covers t = w*32..+31 ----
        const u16* qrow = s_qb + (size_t)(s0 + r4) * QB_STR + 2 * cl;
        u32 a0 = *(const u32*)(qrow);
        u32 a2 = *(const u32*)(qrow + 8);
        u32 a1 = *(const u32*)(qrow + 8 * QB_STR);
        u32 a3 = *(const u32*)(qrow + 8 * QB_STR + 8);
        float4 S[4];
        #pragma unroll
        for (int nb = 0; nb < 4; nb++) {
            int t = w * 32 + nb * 8 + r4;
            const u16* kr = s_kk2 + (size_t)t * KK_STR + 2 * cl;
            u32 b0 = *(const u32*)(kr);
            u32 b1 = *(const u32*)(kr + 8);
            S[nb] = make_float4(0.f, 0.f, 0.f, 0.f);
            mma16bf(S[nb], a0, a1, a2, a3, b0, b1);
        }

        // ---- exp + warp-partial row sums (rows r4 and r4+8) ----
        float eA[8], eB[8];
        float sumA = 0.f, sumB = 0.f;
        #pragma unroll
        for (int nb = 0; nb < 4; nb++) {
            eA[2*nb]   = __expf(S[nb].x); eA[2*nb+1] = __expf(S[nb].y);
            eB[2*nb]   = __expf(S[nb].z); eB[2*nb+1] = __expf(S[nb].w);
            sumA += eA[2*nb] + eA[2*nb+1];
            sumB += eB[2*nb] + eB[2*nb+1];
        }
        sumA += __shfl_xor_sync(0xffffffffu, sumA, 1);
        sumA += __shfl_xor_sync(0xffffffffu, sumA, 2);
        sumB += __shfl_xor_sync(0xffffffffu, sumB, 1);
        sumB += __shfl_xor_sync(0xffffffffu, sumB, 2);
        if (cl == 0) {
            redp[r4 * 16 + w]       = sumA;
            redp[(r4 + 8) * 16 + w] = sumB;
        }

        // ---- store unnormalized exp (tf32) to att ----
        {
            float* arow  = s_att + r4 * ATT_STR + w * 32 + 2 * cl;
            float* arow2 = arow + 8 * ATT_STR;
            #pragma unroll
            for (int nb = 0; nb < 4; nb++) {
                *(float2*)(arow  + nb * 8) = make_float2(tf32r(eA[2*nb]), tf32r(eA[2*nb+1]));
                *(float2*)(arow2 + nb * 8) = make_float2(tf32r(eB[2*nb]), tf32r(eB[2*nb+1]));
            }
        }
        __syncthreads();                               // bar 1: att + red ready

        // ---- out GEMM via tf32 mma: warp = (tq, ds) ----
        float4 D0 = make_float4(0.f, 0.f, 0.f, 0.f);
        float4 D1 = make_float4(0.f, 0.f, 0.f, 0.f);
        #pragma unroll 4
        for (int kc = 0; kc < 16; kc++) {
            const float* ak = aP + kc * 8;
            u32 g0 = __float_as_uint(ak[0]);
            u32 g1 = __float_as_uint(ak[8 * ATT_STR]);
            u32 g2 = __float_as_uint(ak[4]);
            u32 g3 = __float_as_uint(ak[4 + 8 * ATT_STR]);
            const float* bk = bB + kc * 512;
            u32 b00 = __float_as_uint(bk[cb0]);
            u32 b01 = __float_as_uint(bk[256 + cb0]);
            u32 b10 = __float_as_uint(bk[cb1]);
            u32 b11 = __float_as_uint(bk[256 + cb1]);
            mma8(D0, g0, g1, g2, g3, b00, b01);
            mma8(D1, g0, g1, g2, g3, b10, b11);
        }
        {
            int c2 = 2 * cl;
            float* dp = s_D + tq * D_Q + r4 * D_STR + ds * 16;
            *(float2*)(dp + c2)                = make_float2(D0.x, D0.y);
            *(float2*)(dp + c2 + 8 * D_STR)    = make_float2(D0.z, D0.w);
            *(float2*)(dp + c2 + 8)            = make_float2(D1.x, D1.y);
            *(float2*)(dp + c2 + 8 + 8 * D_STR) = make_float2(D1.z, D1.w);
        }
        __syncthreads();                               // bar 2: D ready

        // ---- epilogue: reduce 4 quarters, normalize, add band, store ----
        {
            const float* pD = s_D + srow * D_STR + dloc;
            float2 p0 = *(const float2*)(pD);
            float2 p1 = *(const float2*)(pD + D_Q);
            float2 p2 = *(const float2*)(pD + 2 * D_Q);
            float2 p3 = *(const float2*)(pD + 3 * D_Q);
            float sx = (p0.x + p1.x) + (p2.x + p3.x);
            float sy = (p0.y + p1.y) + (p2.y + p3.y);

            const float4* rr = (const float4*)(redp + srow * 16);
            float4 rA = rr[0], rB = rr[1], rC = rr[2], rD2 = rr[3];
            float rowsum = ((rA.x + rA.y) + (rA.z + rA.w))
                         + ((rB.x + rB.y) + (rB.z + rB.w))
                         + ((rC.x + rC.y) + (rC.z + rC.w))
                         + ((rD2.x + rD2.y) + (rD2.z + rD2.w));
            float inv = 1.0f / rowsum;
            float ox = sx * inv, oy = sy * inv;

            int trow = 2 * (s0 + srow) - 4;
            #pragma unroll
            for (int o = 0; o < 9; o++) {
                int t = trow + o;
                if ((unsigned)t < 512u) {
                    float2 xv = *(const float2*)(s_xp + (size_t)t * 64 + (dloc ^ (8 * (t & 3))));
                    float kw = s_kb[o];
                    ox = fmaf(kw, xv.x, ox);
                    oy = fmaf(kw, xv.y, oy);
                }
            }
            int sidx = s0 + srow;
            size_t ob = (((size_t)n * CC + dloc) * SS + sidx) * VV + v;
            out[ob] = ox;
            out[ob + dstg] = oy;
        }
        // no bar: next tile's att/red writes use the other red buffer and att
        // writes occur before bar1_{i+1}; every thread finishes this epilogue
        // before passing bar1_{i+1}.
    }
}

extern "C" void kernel_launch(void* const* d_in, const int* in_sizes, int n_in,
                              void* d_out, int out_size)
{
    const float* x     = (const float*)d_in[0];
    const float* W     = (const float*)d_in[1];
    const float* alpha = (const float*)d_in[2];
    const float* phi   = (const float*)d_in[3];
    const float* karr  = (const float*)d_in[4];
    float* out = (float*)d_out;

    xpose_kernel<<<dim3(400, 2, 16), dim3(32, 8)>>>(x);

    const int smemB = SMEM_FLOATS * sizeof(float);   // 225856 bytes
    cudaFuncSetAttribute(tgat8_kernel,
                         cudaFuncAttributeMaxDynamicSharedMemorySize, smemB);
    tgat8_kernel<<<NVB, 512, smemB>>>(W, alpha, phi, karr, out);
}

// round 14
// speedup vs baseline: 2.1554x; 1.4904x over previous
#include <cuda_runtime.h>

#define CC 64
#define TT 512
#define VV 25
#define SS 256
#define NVB 400

#define ATT_STRU 260
#define D_STR 66
#define D_Q 1056

#define OFF_KK  16384
#define OFF_Q   20480
#define OFF_ATT 22528
#define OFF_D   26688
#define OFF_RED 30912
#define OFF_KB  31424
#define OFF_OV  31440
#define OFF_W16 35536
#define SMEM_FLOATS 37584          // 150336 bytes

typedef unsigned long long u64;
typedef unsigned int u32;
typedef unsigned short u16;

__device__ float g_xT[(size_t)NVB * TT * CC];   // [n][v][t][c]

__device__ __forceinline__ u64 pk2(float a, float b) {
    u64 r; asm("mov.b64 %0, {%1,%2};" : "=l"(r) : "f"(a), "f"(b)); return r;
}
__device__ __forceinline__ u64 f2(u64 a, u64 b, u64 c) {
    u64 d; asm("fma.rn.f32x2 %0, %1, %2, %3;" : "=l"(d) : "l"(a), "l"(b), "l"(c)); return d;
}
__device__ __forceinline__ u64 ad2(u64 a, u64 b) {
    u64 d; asm("add.rn.f32x2 %0, %1, %2;" : "=l"(d) : "l"(a), "l"(b)); return d;
}
__device__ __forceinline__ float2 up2(u64 a) {
    float lo, hi; asm("mov.b64 {%0,%1}, %2;" : "=f"(lo), "=f"(hi) : "l"(a));
    return make_float2(lo, hi);
}
// pack (hi,lo) fp32 -> fp16x2 (lo in low half)
__device__ __forceinline__ u32 hpk(float hi, float lo) {
    u32 r; asm("cvt.rn.f16x2.f32 %0, %1, %2;" : "=r"(r) : "f"(hi), "f"(lo)); return r;
}
__device__ __forceinline__ float2 h2f2(u32 h) {
    float2 f;
    asm("{.reg .f16 l,u; mov.b32 {l,u}, %2; cvt.f32.f16 %0, l; cvt.f32.f16 %1, u;}"
        : "=f"(f.x), "=f"(f.y) : "r"(h));
    return f;
}
__device__ __forceinline__ void mma16h(float4& d, u32 a0, u32 a1, u32 a2, u32 a3,
                                       u32 b0, u32 b1) {
    asm("mma.sync.aligned.m16n8k16.row.col.f32.f16.f16.f32 "
        "{%0,%1,%2,%3},{%4,%5,%6,%7},{%8,%9},{%0,%1,%2,%3};"
        : "+f"(d.x), "+f"(d.y), "+f"(d.z), "+f"(d.w)
        : "r"(a0), "r"(a1), "r"(a2), "r"(a3), "r"(b0), "r"(b1));
}
__device__ __forceinline__ u64 shflx64(u64 v, int m) {
    u32 lo = (u32)v, hi = (u32)(v >> 32);
    lo = __shfl_xor_sync(0xffffffffu, lo, m);
    hi = __shfl_xor_sync(0xffffffffu, hi, m);
    return ((u64)hi << 32) | lo;
}

// ---------------------------------------------------------------------------
__global__ void __launch_bounds__(256) xpose_kernel(const float* __restrict__ x)
{
    __shared__ float tile[32][33];
    const int n  = blockIdx.z;
    const int c0 = blockIdx.y * 32;
    const int j0 = blockIdx.x * 32;
    const int tx = threadIdx.x, ty = threadIdx.y;

    const float* xb = x + ((size_t)n * CC + c0) * (TT * VV) + j0;
    #pragma unroll
    for (int r = 0; r < 32; r += 8)
        tile[ty + r][tx] = xb[(size_t)(ty + r) * (TT * VV) + tx];
    __syncthreads();

    float* ob = g_xT + (size_t)n * VV * TT * CC;
    #pragma unroll
    for (int r = 0; r < 32; r += 8) {
        int j = j0 + ty + r;
        int t = j / VV, v = j - t * VV;
        ob[((size_t)v * TT + t) * CC + c0 + tx] = tile[tx][ty + r];
    }
}

// ---------------------------------------------------------------------------
__global__ void __launch_bounds__(512, 1) tgat9_kernel(
    const float* __restrict__ W,
    const float* __restrict__ alpha, const float* __restrict__ phi,
    const float* __restrict__ karr, float* __restrict__ out)
{
    extern __shared__ float sm[];
    u32*   xp16 = (u32*)sm;                  // [256 tp][64 d], d ^= 8*(tp&3)
    u32*   kk16 = (u32*)(sm + OFF_KK);       // [512 t][8 jp], jp ^= t&7
    u32*   q16  = (u32*)(sm + OFF_Q);        // [256 s][8 jp], jp ^= s&7
    u32*   at16 = (u32*)(sm + OFF_ATT);      // [16 row][260 tp]
    float* sD   = sm + OFF_D;                // [4][16][66]
    float* sred = sm + OFF_RED;              // [2][256]
    float* skb  = sm + OFF_KB;
    u32*   xs16 = (u32*)(sm + OFF_OV);       // [128 lt][32 cp], cp ^= 4*(lt&7)
    u32*   w16  = (u32*)(sm + OFF_W16);      // [32 cp][64 d], d ^= 8*(cp&3)

    const int tid = threadIdx.x;
    const int nv = blockIdx.x;
    const int n = nv / VV, v = nv - n * VV;
    const int wid = tid >> 5, wl = tid & 31;
    const int r4 = wl >> 2, cl = wl & 3;

    // ---------- phase 0: W -> w16 fp16 c-pair packed ----------
    {
        int cp = tid >> 4;
        int d0 = (tid & 15) * 4;
        float4 wa = *(const float4*)(W + (2 * cp) * 64 + d0);
        float4 wb = *(const float4*)(W + (2 * cp + 1) * 64 + d0);
        int sw = 8 * (cp & 3);
        w16[cp * 64 + ((d0 + 0) ^ sw)] = hpk(wb.x, wa.x);
        w16[cp * 64 + ((d0 + 1) ^ sw)] = hpk(wb.y, wa.y);
        w16[cp * 64 + ((d0 + 2) ^ sw)] = hpk(wb.z, wa.z);
        w16[cp * 64 + ((d0 + 3) ^ sw)] = hpk(wb.w, wa.w);
    }
    if (tid < 16) skb[tid] = (tid < 9) ? karr[tid] : 0.0f;

    // ---------- phase 1: xp = x @ W via fp16 mma, 4 chunks of 128 t ----------
    const float* xTb = g_xT + (size_t)nv * TT * CC;
    const int tl = tid >> 4, c4 = tid & 15;
    float4 g[4];
    #pragma unroll
    for (int k = 0; k < 4; k++)
        g[k] = *(const float4*)(xTb + ((size_t)(k * 32 + tl) * CC + c4 * 4));
    // stage chunk 0
    #pragma unroll
    for (int k = 0; k < 4; k++) {
        int lt = k * 32 + tl;
        int sw = 4 * (lt & 7);
        u32 lo = hpk(g[k].y, g[k].x);
        u32 hi = hpk(g[k].w, g[k].z);
        *(u64*)(xs16 + lt * 32 + ((2 * c4) ^ sw)) = ((u64)hi << 32) | lo;
    }
    __syncthreads();

    const int mt = wid >> 1, nh = wid & 1;
    // preload W fragments (held across chunks)
    u32 WB[4][4][2];
    #pragma unroll
    for (int nb = 0; nb < 4; nb++)
        #pragma unroll
        for (int kc = 0; kc < 4; kc++) {
            int cp = kc * 8 + cl;
            int d = nh * 32 + nb * 8 + r4;
            WB[nb][kc][0] = w16[cp * 64 + (d ^ (8 * cl))];
            WB[nb][kc][1] = w16[(cp + 4) * 64 + (d ^ (8 * cl))];
        }

    for (int ch = 0; ch < 4; ch++) {
        if (ch < 3) {
            int tb = (ch + 1) * 128;
            #pragma unroll
            for (int k = 0; k < 4; k++)
                g[k] = *(const float4*)(xTb + ((size_t)(tb + k * 32 + tl) * CC + c4 * 4));
        }
        float4 Dx[4];
        #pragma unroll
        for (int nb = 0; nb < 4; nb++) Dx[nb] = make_float4(0.f, 0.f, 0.f, 0.f);
        const int lt0 = mt * 16 + r4;
        const int swa = 4 * r4;
        #pragma unroll
        for (int kc = 0; kc < 4; kc++) {
            u32 a0 = xs16[lt0 * 32 + ((kc * 8 + cl) ^ swa)];
            u32 a1 = xs16[(lt0 + 8) * 32 + ((kc * 8 + cl) ^ swa)];
            u32 a2 = xs16[lt0 * 32 + ((kc * 8 + cl + 4) ^ swa)];
            u32 a3 = xs16[(lt0 + 8) * 32 + ((kc * 8 + cl + 4) ^ swa)];
            #pragma unroll
            for (int nb = 0; nb < 4; nb++)
                mma16h(Dx[nb], a0, a1, a2, a3, WB[nb][kc][0], WB[nb][kc][1]);
        }
        // pack t-pairs via shfl, store xp16
        {
            int gt = ch * 128 + mt * 16 + r4;
            int tp = gt >> 1;
            int sw = 8 * (tp & 3);
            bool even = ((r4 & 1) == 0);
            #pragma unroll
            for (int nb = 0; nb < 4; nb++) {
                int dc = nh * 32 + nb * 8 + 2 * cl;
                float o0 = __shfl_xor_sync(0xffffffffu, Dx[nb].x, 4);
                float o1 = __shfl_xor_sync(0xffffffffu, Dx[nb].y, 4);
                float o2 = __shfl_xor_sync(0xffffffffu, Dx[nb].z, 4);
                float o3 = __shfl_xor_sync(0xffffffffu, Dx[nb].w, 4);
                if (even) {
                    u32 p0 = hpk(o0, Dx[nb].x);
                    u32 p1 = hpk(o1, Dx[nb].y);
                    u32 p2 = hpk(o2, Dx[nb].z);
                    u32 p3 = hpk(o3, Dx[nb].w);
                    *(u64*)(xp16 + tp * 64 + (dc ^ sw))       = ((u64)p1 << 32) | p0;
                    *(u64*)(xp16 + (tp + 4) * 64 + (dc ^ sw)) = ((u64)p3 << 32) | p2;
                }
            }
        }
        if (ch < 3) {
            __syncthreads();                 // xs reads done
            #pragma unroll
            for (int k = 0; k < 4; k++) {
                int lt = k * 32 + tl;
                int sw = 4 * (lt & 7);
                u32 lo = hpk(g[k].y, g[k].x);
                u32 hi = hpk(g[k].w, g[k].z);
                *(u64*)(xs16 + lt * 32 + ((2 * c4) ^ sw)) = ((u64)hi << 32) | lo;
            }
            __syncthreads();                 // xs ready
        }
    }
    __syncthreads();                         // xp16 complete

    // ---------- phase 2: kk = xp@phi ; q = xp@alpha/16 (fp16 outputs) ----------
    float* sAl = sm + OFF_OV;
    float* sPh = sm + OFF_OV + 1024;
    for (int i = tid; i < 1024; i += 512) { sAl[i] = alpha[i] * 0.0625f; sPh[i] = phi[i]; }
    __syncthreads();
    {
        const int tp = tid >> 1, hf = tid & 1;
        const int s4 = tp & 3;
        u64 k0[8], k1[8], qa[8];
        #pragma unroll
        for (int j = 0; j < 8; j++) { k0[j] = pk2(0.f, 0.f); k1[j] = k0[j]; qa[j] = k0[j]; }
        #pragma unroll
        for (int b = 0; b < 4; b++) {
            int kb = (b ^ s4) * 8 + hf * 32;
            uint4 va = *(const uint4*)(xp16 + tp * 64 + kb);
            uint4 vb = *(const uint4*)(xp16 + tp * 64 + kb + 4);
            u32 uu[8] = {va.x, va.y, va.z, va.w, vb.x, vb.y, vb.z, vb.w};
            #pragma unroll
            for (int i = 0; i < 8; i++) {
                int d = hf * 32 + b * 8 + i;
                float2 xv = h2f2(uu[i]);
                u64 x0 = pk2(xv.x, xv.x), x1 = pk2(xv.y, xv.y);
                const ulonglong2* pp = (const ulonglong2*)(sPh + d * 16);
                ulonglong2 p0 = pp[0], p1 = pp[1], p2 = pp[2], p3 = pp[3];
                k0[0] = f2(x0, p0.x, k0[0]); k0[1] = f2(x0, p0.y, k0[1]);
                k0[2] = f2(x0, p1.x, k0[2]); k0[3] = f2(x0, p1.y, k0[3]);
                k0[4] = f2(x0, p2.x, k0[4]); k0[5] = f2(x0, p2.y, k0[5]);
                k0[6] = f2(x0, p3.x, k0[6]); k0[7] = f2(x0, p3.y, k0[7]);
                k1[0] = f2(x1, p0.x, k1[0]); k1[1] = f2(x1, p0.y, k1[1]);
                k1[2] = f2(x1, p1.x, k1[2]); k1[3] = f2(x1, p1.y, k1[3]);
                k1[4] = f2(x1, p2.x, k1[4]); k1[5] = f2(x1, p2.y, k1[5]);
                k1[6] = f2(x1, p3.x, k1[6]); k1[7] = f2(x1, p3.y, k1[7]);
                const ulonglong2* aa = (const ulonglong2*)(sAl + d * 16);
                ulonglong2 a0 = aa[0], a1 = aa[1], a2 = aa[2], a3 = aa[3];
                qa[0] = f2(x0, a0.x, qa[0]); qa[1] = f2(x0, a0.y, qa[1]);
                qa[2] = f2(x0, a1.x, qa[2]); qa[3] = f2(x0, a1.y, qa[3]);
                qa[4] = f2(x0, a2.x, qa[4]); qa[5] = f2(x0, a2.y, qa[5]);
                qa[6] = f2(x0, a3.x, qa[6]); qa[7] = f2(x0, a3.y, qa[7]);
            }
        }
        #pragma unroll
        for (int j = 0; j < 8; j++) {
            k0[j] = ad2(k0[j], shflx64(k0[j], 1));
            k1[j] = ad2(k1[j], shflx64(k1[j], 1));
            qa[j] = ad2(qa[j], shflx64(qa[j], 1));
        }
        int t0 = 2 * tp;
        if (hf == 0) {
            #pragma unroll
            for (int jp = 0; jp < 8; jp++) {
                float2 kv = up2(k0[jp]);
                kk16[t0 * 8 + (jp ^ (t0 & 7))] = hpk(kv.y, kv.x);
                float2 qv = up2(qa[jp]);
                q16[tp * 8 + (jp ^ (tp & 7))] = hpk(qv.y, qv.x);
            }
        } else {
            #pragma unroll
            for (int jp = 0; jp < 8; jp++) {
                float2 kv = up2(k1[jp]);
                kk16[(t0 + 1) * 8 + (jp ^ ((t0 + 1) & 7))] = hpk(kv.y, kv.x);
            }
        }
    }
    __syncthreads();

    // ---------- phase 3: 16 tiles of 16 s-rows ----------
    const int w = wid;
    const int tq = w & 3, ds = w >> 2;
    const int srow = tid >> 5, dloc = (tid & 31) * 2;
    const size_t dstg = (size_t)SS * VV;

    for (int tile = 0; tile < 16; tile++) {
        const int s0 = tile * 16;
        float* redp = sred + (tile & 1) * 256;

        // ---- scores via fp16 mma: warp covers t = w*32..+31 ----
        {
            int qr = s0 + r4;
            u32 a0 = q16[qr * 8 + (cl ^ r4)];
            u32 a1 = q16[(qr + 8) * 8 + (cl ^ r4)];
            u32 a2 = q16[qr * 8 + ((cl + 4) ^ r4)];
            u32 a3 = q16[(qr + 8) * 8 + ((cl + 4) ^ r4)];
            float4 S[4];
            #pragma unroll
            for (int nb = 0; nb < 4; nb++) {
                int t = w * 32 + nb * 8 + r4;
                u32 b0 = kk16[t * 8 + (cl ^ r4)];
                u32 b1 = kk16[t * 8 + ((cl + 4) ^ r4)];
                S[nb] = make_float4(0.f, 0.f, 0.f, 0.f);
                mma16h(S[nb], a0, a1, a2, a3, b0, b1);
            }
            float eA[8], eB[8], sumA = 0.f, sumB = 0.f;
            #pragma unroll
            for (int nb = 0; nb < 4; nb++) {
                eA[2*nb]   = __expf(S[nb].x); eA[2*nb+1] = __expf(S[nb].y);
                eB[2*nb]   = __expf(S[nb].z); eB[2*nb+1] = __expf(S[nb].w);
                sumA += eA[2*nb] + eA[2*nb+1];
                sumB += eB[2*nb] + eB[2*nb+1];
            }
            sumA += __shfl_xor_sync(0xffffffffu, sumA, 1);
            sumA += __shfl_xor_sync(0xffffffffu, sumA, 2);
            sumB += __shfl_xor_sync(0xffffffffu, sumB, 1);
            sumB += __shfl_xor_sync(0xffffffffu, sumB, 2);
            if (cl == 0) {
                redp[r4 * 16 + w]       = sumA;
                redp[(r4 + 8) * 16 + w] = sumB;
            }
            #pragma unroll
            for (int nb = 0; nb < 4; nb++) {
                at16[r4 * ATT_STRU + w * 16 + nb * 4 + cl]       = hpk(eA[2*nb+1], eA[2*nb]);
                at16[(r4 + 8) * ATT_STRU + w * 16 + nb * 4 + cl] = hpk(eB[2*nb+1], eB[2*nb]);
            }
        }
        __syncthreads();                               // bar 1: att + red ready

        // ---- out GEMM via fp16 mma: warp = (tq, ds) ----
        float4 D0 = make_float4(0.f, 0.f, 0.f, 0.f);
        float4 D1 = make_float4(0.f, 0.f, 0.f, 0.f);
        #pragma unroll 4
        for (int kc = 0; kc < 8; kc++) {
            int tpb = tq * 64 + kc * 8;
            u32 g0 = at16[r4 * ATT_STRU + tpb + cl];
            u32 g1 = at16[(r4 + 8) * ATT_STRU + tpb + cl];
            u32 g2 = at16[r4 * ATT_STRU + tpb + cl + 4];
            u32 g3 = at16[(r4 + 8) * ATT_STRU + tpb + cl + 4];
            int d0i = ds * 16 + r4;
            int swb = 8 * cl;
            u32 b00 = xp16[(tpb + cl) * 64 + (d0i ^ swb)];
            u32 b01 = xp16[(tpb + cl + 4) * 64 + (d0i ^ swb)];
            u32 b10 = xp16[(tpb + cl) * 64 + ((d0i + 8) ^ swb)];
            u32 b11 = xp16[(tpb + cl + 4) * 64 + ((d0i + 8) ^ swb)];
            mma16h(D0, g0, g1, g2, g3, b00, b01);
            mma16h(D1, g0, g1, g2, g3, b10, b11);
        }
        {
            int c2 = 2 * cl;
            float* dp = sD + tq * D_Q + r4 * D_STR + ds * 16;
            *(float2*)(dp + c2)                 = make_float2(D0.x, D0.y);
            *(float2*)(dp + c2 + 8 * D_STR)     = make_float2(D0.z, D0.w);
            *(float2*)(dp + c2 + 8)             = make_float2(D1.x, D1.y);
            *(float2*)(dp + c2 + 8 + 8 * D_STR) = make_float2(D1.z, D1.w);
        }
        __syncthreads();                               // bar 2: D ready

        // ---- epilogue: reduce quarters, normalize, add band, store ----
        {
            const float* pD = sD + srow * D_STR + dloc;
            float2 p0 = *(const float2*)(pD);
            float2 p1 = *(const float2*)(pD + D_Q);
            float2 p2 = *(const float2*)(pD + 2 * D_Q);
            float2 p3 = *(const float2*)(pD + 3 * D_Q);
            float sx = (p0.x + p1.x) + (p2.x + p3.x);
            float sy = (p0.y + p1.y) + (p2.y + p3.y);

            const float4* rr = (const float4*)(redp + srow * 16);
            float4 rA = rr[0], rB = rr[1], rC = rr[2], rD2 = rr[3];
            float rowsum = ((rA.x + rA.y) + (rA.z + rA.w))
                         + ((rB.x + rB.y) + (rB.z + rB.w))
                         + ((rC.x + rC.y) + (rC.z + rC.w))
                         + ((rD2.x + rD2.y) + (rD2.z + rD2.w));
            float inv = 1.0f / rowsum;
            float ox = sx * inv, oy = sy * inv;

            int trow = 2 * (s0 + srow) - 4;            // even
            #pragma unroll
            for (int i = 0; i < 5; i++) {
                int t0 = trow + 2 * i;
                if ((unsigned)t0 <= 510u) {
                    int tp = t0 >> 1;
                    u64 xv = *(const u64*)(xp16 + tp * 64 + (dloc ^ (8 * (tp & 3))));
                    float2 xa = h2f2((u32)xv);         // d = dloc : (t0, t0+1)
                    float2 xb = h2f2((u32)(xv >> 32)); // d = dloc+1
                    float w0 = skb[2 * i], w1 = skb[2 * i + 1];
                    ox = fmaf(w0, xa.x, fmaf(w1, xa.y, ox));
                    oy = fmaf(w0, xb.x, fmaf(w1, xb.y, oy));
                }
            }
            int sidx = s0 + srow;
            size_t ob = (((size_t)n * CC + dloc) * SS + sidx) * VV + v;
            out[ob] = ox;
            out[ob + dstg] = oy;
        }
        // no bar: epilogue reads complete before any thread passes next bar 1;
        // red double-buffered by tile parity.
    }
}

extern "C" void kernel_launch(void* const* d_in, const int* in_sizes, int n_in,
                              void* d_out, int out_size)
{
    const float* x     = (const float*)d_in[0];
    const float* W     = (const float*)d_in[1];
    const float* alpha = (const float*)d_in[2];
    const float* phi   = (const float*)d_in[3];
    const float* karr  = (const float*)d_in[4];
    float* out = (float*)d_out;

    xpose_kernel<<<dim3(400, 2, 16), dim3(32, 8)>>>(x);

    const int smemB = SMEM_FLOATS * sizeof(float);   // 150336 bytes
    cudaFuncSetAttribute(tgat9_kernel,
                         cudaFuncAttributeMaxDynamicSharedMemorySize, smemB);
    tgat9_kernel<<<NVB, 512, smemB>>>(W, alpha, phi, karr, out);
}

// round 15
// speedup vs baseline: 2.2012x; 1.0213x over previous
#include <cuda_runtime.h>

#define CC 64
#define TT 512
#define VV 25
#define SS 256
#define NVB 400

#define ATT_STRU 260
#define ATT_BUF  4160
#define D_STR 66
#define D_Q   1056
#define D_BUF 4224

#define OFF_KK  16384
#define OFF_Q   20480
#define OFF_ATT 22528
#define OFF_D   30848
#define OFF_RED 39296
#define OFF_KB  40320
#define SMEM_FLOATS 40336          // 161344 bytes
#define OFF_OV  22528              // overlay: xs16 (phase1), sAl/sPh (phase2)
#define OFF_W16 26624              // overlay: w16 (phase1)

typedef unsigned long long u64;
typedef unsigned int u32;
typedef unsigned short u16;

__device__ u32 g_xT16[(size_t)NVB * TT * 32];   // [n][v][t][c-pair] fp16x2, 26.2 MB

__device__ __forceinline__ u64 pk2(float a, float b) {
    u64 r; asm("mov.b64 %0, {%1,%2};" : "=l"(r) : "f"(a), "f"(b)); return r;
}
__device__ __forceinline__ u64 f2(u64 a, u64 b, u64 c) {
    u64 d; asm("fma.rn.f32x2 %0, %1, %2, %3;" : "=l"(d) : "l"(a), "l"(b), "l"(c)); return d;
}
__device__ __forceinline__ u64 ad2(u64 a, u64 b) {
    u64 d; asm("add.rn.f32x2 %0, %1, %2;" : "=l"(d) : "l"(a), "l"(b)); return d;
}
__device__ __forceinline__ float2 up2(u64 a) {
    float lo, hi; asm("mov.b64 {%0,%1}, %2;" : "=f"(lo), "=f"(hi) : "l"(a));
    return make_float2(lo, hi);
}
__device__ __forceinline__ u32 hpk(float hi, float lo) {
    u32 r; asm("cvt.rn.f16x2.f32 %0, %1, %2;" : "=r"(r) : "f"(hi), "f"(lo)); return r;
}
__device__ __forceinline__ float2 h2f2(u32 h) {
    float2 f;
    asm("{.reg .f16 l,u; mov.b32 {l,u}, %2; cvt.f32.f16 %0, l; cvt.f32.f16 %1, u;}"
        : "=f"(f.x), "=f"(f.y) : "r"(h));
    return f;
}
__device__ __forceinline__ void mma16h(float4& d, u32 a0, u32 a1, u32 a2, u32 a3,
                                       u32 b0, u32 b1) {
    asm("mma.sync.aligned.m16n8k16.row.col.f32.f16.f16.f32 "
        "{%0,%1,%2,%3},{%4,%5,%6,%7},{%8,%9},{%0,%1,%2,%3};"
        : "+f"(d.x), "+f"(d.y), "+f"(d.z), "+f"(d.w)
        : "r"(a0), "r"(a1), "r"(a2), "r"(a3), "r"(b0), "r"(b1));
}
__device__ __forceinline__ u64 shflx64(u64 v, int m) {
    u32 lo = (u32)v, hi = (u32)(v >> 32);
    lo = __shfl_xor_sync(0xffffffffu, lo, m);
    hi = __shfl_xor_sync(0xffffffffu, hi, m);
    return ((u64)hi << 32) | lo;
}

// ---------------------------------------------------------------------------
// Transpose: x[n][c][t][v] -> g_xT16[n][v][t][c-pair] (fp16x2)
// ---------------------------------------------------------------------------
__global__ void __launch_bounds__(256) xpose16_kernel(const float* __restrict__ x)
{
    __shared__ float tile[32][33];
    const int n  = blockIdx.z;
    const int c0 = blockIdx.y * 32;
    const int j0 = blockIdx.x * 32;
    const int tx = threadIdx.x, ty = threadIdx.y;

    const float* xb = x + ((size_t)n * CC + c0) * (TT * VV) + j0;
    #pragma unroll
    for (int r = 0; r < 32; r += 8)
        tile[ty + r][tx] = xb[(size_t)(ty + r) * (TT * VV) + tx];
    __syncthreads();

    const int idx = ty * 32 + tx;
    u32* ob = g_xT16 + (size_t)n * VV * TT * 32 + (c0 >> 1);
    #pragma unroll
    for (int i = 0; i < 2; i++) {
        int id = idx + i * 256;
        int j = id >> 4;               // 0..31
        int cp = id & 15;              // 0..15
        int jj = j0 + j;
        int t = jj / VV, v = jj - t * VV;
        u32 val = hpk(tile[2 * cp + 1][j], tile[2 * cp][j]);
        ob[((size_t)v * TT + t) * 32 + cp] = val;
    }
}

// ---------------------------------------------------------------------------
__global__ void __launch_bounds__(512, 1) tgatA_kernel(
    const float* __restrict__ W,
    const float* __restrict__ alpha, const float* __restrict__ phi,
    const float* __restrict__ karr, float* __restrict__ out)
{
    extern __shared__ float sm[];
    u32*   xp16 = (u32*)sm;                  // [256 tp][64 d], d ^= 8*(tp&3)
    u32*   kk16 = (u32*)(sm + OFF_KK);       // [512 t][8 jp], jp ^= t&7
    u32*   q16  = (u32*)(sm + OFF_Q);        // [256 s][8 jp], jp ^= s&7
    u32*   at16 = (u32*)(sm + OFF_ATT);      // 2 x [16 row][260 tp]
    float* sD   = sm + OFF_D;                // 2 x [4][16][66]
    float* sred = sm + OFF_RED;              // 4 x [256]
    float* skb  = sm + OFF_KB;
    u32*   xs16 = (u32*)(sm + OFF_OV);       // [128 lt][32 cp], cp ^= 4*(lt&7)
    u32*   w16  = (u32*)(sm + OFF_W16);      // [32 cp][64 d], d ^= 8*(cp&3)

    const int tid = threadIdx.x;
    const int nv = blockIdx.x;
    const int n = nv / VV, v = nv - n * VV;
    const int wid = tid >> 5, wl = tid & 31;
    const int r4 = wl >> 2, cl = wl & 3;

    // ---------- phase 0: W -> w16 fp16 c-pair packed ----------
    {
        int cp = tid >> 4;
        int d0 = (tid & 15) * 4;
        float4 wa = *(const float4*)(W + (2 * cp) * 64 + d0);
        float4 wb = *(const float4*)(W + (2 * cp + 1) * 64 + d0);
        int sw = 8 * (cp & 3);
        w16[cp * 64 + ((d0 + 0) ^ sw)] = hpk(wb.x, wa.x);
        w16[cp * 64 + ((d0 + 1) ^ sw)] = hpk(wb.y, wa.y);
        w16[cp * 64 + ((d0 + 2) ^ sw)] = hpk(wb.z, wa.z);
        w16[cp * 64 + ((d0 + 3) ^ sw)] = hpk(wb.w, wa.w);
    }
    if (tid < 16) skb[tid] = (tid < 9) ? karr[tid] : 0.0f;

    // ---------- phase 1: xp = x @ W via fp16 mma, 4 chunks of 128 t ----------
    const u32* xTb = g_xT16 + (size_t)nv * TT * 32;
    const int p1row = tid >> 2;              // 0..127
    const int p1q   = (tid & 3) * 8;         // u32 col base
    uint4 ga, gb;
    {
        const u32* p = xTb + (size_t)p1row * 32 + p1q;
        ga = *(const uint4*)p; gb = *(const uint4*)(p + 4);
    }
    {
        int sw = 4 * (p1row & 7);
        u32* b = xs16 + p1row * 32;
        *(u64*)(b + ((p1q + 0) ^ sw)) = ((u64)ga.y << 32) | ga.x;
        *(u64*)(b + ((p1q + 2) ^ sw)) = ((u64)ga.w << 32) | ga.z;
        *(u64*)(b + ((p1q + 4) ^ sw)) = ((u64)gb.y << 32) | gb.x;
        *(u64*)(b + ((p1q + 6) ^ sw)) = ((u64)gb.w << 32) | gb.z;
    }
    __syncthreads();

    const int mt = wid >> 1, nh = wid & 1;
    u32 WB[4][4][2];
    #pragma unroll
    for (int nb = 0; nb < 4; nb++)
        #pragma unroll
        for (int kc = 0; kc < 4; kc++) {
            int cp = kc * 8 + cl;
            int d = nh * 32 + nb * 8 + r4;
            WB[nb][kc][0] = w16[cp * 64 + (d ^ (8 * cl))];
            WB[nb][kc][1] = w16[(cp + 4) * 64 + (d ^ (8 * cl))];
        }

    for (int ch = 0; ch < 4; ch++) {
        if (ch < 3) {
            const u32* p = xTb + (size_t)((ch + 1) * 128 + p1row) * 32 + p1q;
            ga = *(const uint4*)p; gb = *(const uint4*)(p + 4);
        }
        float4 Dx[4];
        #pragma unroll
        for (int nb = 0; nb < 4; nb++) Dx[nb] = make_float4(0.f, 0.f, 0.f, 0.f);
        const int lt0 = mt * 16 + r4;
        const int swa = 4 * r4;
        #pragma unroll
        for (int kc = 0; kc < 4; kc++) {
            u32 a0 = xs16[lt0 * 32 + ((kc * 8 + cl) ^ swa)];
            u32 a1 = xs16[(lt0 + 8) * 32 + ((kc * 8 + cl) ^ swa)];
            u32 a2 = xs16[lt0 * 32 + ((kc * 8 + cl + 4) ^ swa)];
            u32 a3 = xs16[(lt0 + 8) * 32 + ((kc * 8 + cl + 4) ^ swa)];
            #pragma unroll
            for (int nb = 0; nb < 4; nb++)
                mma16h(Dx[nb], a0, a1, a2, a3, WB[nb][kc][0], WB[nb][kc][1]);
        }
        {
            int gt = ch * 128 + mt * 16 + r4;
            int tp = gt >> 1;
            int sw = 8 * (tp & 3);
            bool even = ((r4 & 1) == 0);
            #pragma unroll
            for (int nb = 0; nb < 4; nb++) {
                int dc = nh * 32 + nb * 8 + 2 * cl;
                float o0 = __shfl_xor_sync(0xffffffffu, Dx[nb].x, 4);
                float o1 = __shfl_xor_sync(0xffffffffu, Dx[nb].y, 4);
                float o2 = __shfl_xor_sync(0xffffffffu, Dx[nb].z, 4);
                float o3 = __shfl_xor_sync(0xffffffffu, Dx[nb].w, 4);
                if (even) {
                    u32 p0 = hpk(o0, Dx[nb].x);
                    u32 p1 = hpk(o1, Dx[nb].y);
                    u32 p2 = hpk(o2, Dx[nb].z);
                    u32 p3 = hpk(o3, Dx[nb].w);
                    *(u64*)(xp16 + tp * 64 + (dc ^ sw))       = ((u64)p1 << 32) | p0;
                    *(u64*)(xp16 + (tp + 4) * 64 + (dc ^ sw)) = ((u64)p3 << 32) | p2;
                }
            }
        }
        if (ch < 3) {
            __syncthreads();
            int sw = 4 * (p1row & 7);
            u32* b = xs16 + p1row * 32;
            *(u64*)(b + ((p1q + 0) ^ sw)) = ((u64)ga.y << 32) | ga.x;
            *(u64*)(b + ((p1q + 2) ^ sw)) = ((u64)ga.w << 32) | ga.z;
            *(u64*)(b + ((p1q + 4) ^ sw)) = ((u64)gb.y << 32) | gb.x;
            *(u64*)(b + ((p1q + 6) ^ sw)) = ((u64)gb.w << 32) | gb.z;
            __syncthreads();
        }
    }
    __syncthreads();                         // xp16 complete

    // ---------- phase 2: kk = xp@phi ; q = xp@alpha/16 (fp16 outputs) ----------
    float* sAl = sm + OFF_OV;
    float* sPh = sm + OFF_OV + 1024;
    for (int i = tid; i < 1024; i += 512) { sAl[i] = alpha[i] * 0.0625f; sPh[i] = phi[i]; }
    __syncthreads();
    {
        const int tp = tid >> 1, hf = tid & 1;
        const int s4 = tp & 3;
        u64 k0[8], k1[8], qa[8];
        #pragma unroll
        for (int j = 0; j < 8; j++) { k0[j] = pk2(0.f, 0.f); k1[j] = k0[j]; qa[j] = k0[j]; }
        #pragma unroll
        for (int b = 0; b < 4; b++) {
            int kb = (b ^ s4) * 8 + hf * 32;
            uint4 va = *(const uint4*)(xp16 + tp * 64 + kb);
            uint4 vb = *(const uint4*)(xp16 + tp * 64 + kb + 4);
            u32 uu[8] = {va.x, va.y, va.z, va.w, vb.x, vb.y, vb.z, vb.w};
            #pragma unroll
            for (int i = 0; i < 8; i++) {
                int d = hf * 32 + b * 8 + i;
                float2 xv = h2f2(uu[i]);
                u64 x0 = pk2(xv.x, xv.x), x1 = pk2(xv.y, xv.y);
                const ulonglong2* pp = (const ulonglong2*)(sPh + d * 16);
                ulonglong2 p0 = pp[0], p1 = pp[1], p2 = pp[2], p3 = pp[3];
                k0[0] = f2(x0, p0.x, k0[0]); k0[1] = f2(x0, p0.y, k0[1]);
                k0[2] = f2(x0, p1.x, k0[2]); k0[3] = f2(x0, p1.y, k0[3]);
                k0[4] = f2(x0, p2.x, k0[4]); k0[5] = f2(x0, p2.y, k0[5]);
                k0[6] = f2(x0, p3.x, k0[6]); k0[7] = f2(x0, p3.y, k0[7]);
                k1[0] = f2(x1, p0.x, k1[0]); k1[1] = f2(x1, p0.y, k1[1]);
                k1[2] = f2(x1, p1.x, k1[2]); k1[3] = f2(x1, p1.y, k1[3]);
                k1[4] = f2(x1, p2.x, k1[4]); k1[5] = f2(x1, p2.y, k1[5]);
                k1[6] = f2(x1, p3.x, k1[6]); k1[7] = f2(x1, p3.y, k1[7]);
                const ulonglong2* aa = (const ulonglong2*)(sAl + d * 16);
                ulonglong2 a0 = aa[0], a1 = aa[1], a2 = aa[2], a3 = aa[3];
                qa[0] = f2(x0, a0.x, qa[0]); qa[1] = f2(x0, a0.y, qa[1]);
                qa[2] = f2(x0, a1.x, qa[2]); qa[3] = f2(x0, a1.y, qa[3]);
                qa[4] = f2(x0, a2.x, qa[4]); qa[5] = f2(x0, a2.y, qa[5]);
                qa[6] = f2(x0, a3.x, qa[6]); qa[7] = f2(x0, a3.y, qa[7]);
            }
        }
        #pragma unroll
        for (int j = 0; j < 8; j++) {
            k0[j] = ad2(k0[j], shflx64(k0[j], 1));
            k1[j] = ad2(k1[j], shflx64(k1[j], 1));
            qa[j] = ad2(qa[j], shflx64(qa[j], 1));
        }
        int t0 = 2 * tp;
        if (hf == 0) {
            #pragma unroll
            for (int jp = 0; jp < 8; jp++) {
                float2 kv = up2(k0[jp]);
                kk16[t0 * 8 + (jp ^ (t0 & 7))] = hpk(kv.y, kv.x);
                float2 qv = up2(qa[jp]);
                q16[tp * 8 + (jp ^ (tp & 7))] = hpk(qv.y, qv.x);
            }
        } else {
            #pragma unroll
            for (int jp = 0; jp < 8; jp++) {
                float2 kv = up2(k1[jp]);
                kk16[(t0 + 1) * 8 + (jp ^ ((t0 + 1) & 7))] = hpk(kv.y, kv.x);
            }
        }
    }
    __syncthreads();

    // ---------- phase 3: 16 tiles, software-pipelined, 1 bar/tile ----------
    const int w = wid;
    const int tq = w & 3, ds = w >> 2;
    const int srow = tid >> 5, dloc = (tid & 31) * 2;
    const size_t dstg = (size_t)SS * VV;

    auto do_scores = [&](int tile) {
        int s0 = tile * 16;
        u32* ab = at16 + (tile & 1) * ATT_BUF;
        float* redp = sred + (tile & 3) * 256;
        int qr = s0 + r4;
        u32 a0 = q16[qr * 8 + (cl ^ r4)];
        u32 a1 = q16[(qr + 8) * 8 + (cl ^ r4)];
        u32 a2 = q16[qr * 8 + ((cl + 4) ^ r4)];
        u32 a3 = q16[(qr + 8) * 8 + ((cl + 4) ^ r4)];
        float4 S[4];
        #pragma unroll
        for (int nb = 0; nb < 4; nb++) {
            int t = w * 32 + nb * 8 + r4;
            u32 b0 = kk16[t * 8 + (cl ^ r4)];
            u32 b1 = kk16[t * 8 + ((cl + 4) ^ r4)];
            S[nb] = make_float4(0.f, 0.f, 0.f, 0.f);
            mma16h(S[nb], a0, a1, a2, a3, b0, b1);
        }
        float eA[8], eB[8], sumA = 0.f, sumB = 0.f;
        #pragma unroll
        for (int nb = 0; nb < 4; nb++) {
            eA[2*nb]   = __expf(S[nb].x); eA[2*nb+1] = __expf(S[nb].y);
            eB[2*nb]   = __expf(S[nb].z); eB[2*nb+1] = __expf(S[nb].w);
            sumA += eA[2*nb] + eA[2*nb+1];
            sumB += eB[2*nb] + eB[2*nb+1];
        }
        sumA += __shfl_xor_sync(0xffffffffu, sumA, 1);
        sumA += __shfl_xor_sync(0xffffffffu, sumA, 2);
        sumB += __shfl_xor_sync(0xffffffffu, sumB, 1);
        sumB += __shfl_xor_sync(0xffffffffu, sumB, 2);
        if (cl == 0) {
            redp[r4 * 16 + w]       = sumA;
            redp[(r4 + 8) * 16 + w] = sumB;
        }
        #pragma unroll
        for (int nb = 0; nb < 4; nb++) {
            ab[r4 * ATT_STRU + w * 16 + nb * 4 + cl]       = hpk(eA[2*nb+1], eA[2*nb]);
            ab[(r4 + 8) * ATT_STRU + w * 16 + nb * 4 + cl] = hpk(eB[2*nb+1], eB[2*nb]);
        }
    };

    auto do_gemm = [&](int tile) {
        const u32* ab = at16 + (tile & 1) * ATT_BUF;
        float* Db = sD + (tile & 1) * D_BUF;
        float4 D0 = make_float4(0.f, 0.f, 0.f, 0.f);
        float4 D1 = make_float4(0.f, 0.f, 0.f, 0.f);
        #pragma unroll 4
        for (int kc = 0; kc < 8; kc++) {
            int tpb = tq * 64 + kc * 8;
            u32 g0 = ab[r4 * ATT_STRU + tpb + cl];
            u32 g1 = ab[(r4 + 8) * ATT_STRU + tpb + cl];
            u32 g2 = ab[r4 * ATT_STRU + tpb + cl + 4];
            u32 g3 = ab[(r4 + 8) * ATT_STRU + tpb + cl + 4];
            int d0i = ds * 16 + r4;
            int swb = 8 * cl;
            u32 b00 = xp16[(tpb + cl) * 64 + (d0i ^ swb)];
            u32 b01 = xp16[(tpb + cl + 4) * 64 + (d0i ^ swb)];
            u32 b10 = xp16[(tpb + cl) * 64 + ((d0i + 8) ^ swb)];
            u32 b11 = xp16[(tpb + cl + 4) * 64 + ((d0i + 8) ^ swb)];
            mma16h(D0, g0, g1, g2, g3, b00, b01);
            mma16h(D1, g0, g1, g2, g3, b10, b11);
        }
        int c2 = 2 * cl;
        float* dp = Db + tq * D_Q + r4 * D_STR + ds * 16;
        *(float2*)(dp + c2)                 = make_float2(D0.x, D0.y);
        *(float2*)(dp + c2 + 8 * D_STR)     = make_float2(D0.z, D0.w);
        *(float2*)(dp + c2 + 8)             = make_float2(D1.x, D1.y);
        *(float2*)(dp + c2 + 8 + 8 * D_STR) = make_float2(D1.z, D1.w);
    };

    auto do_epi = [&](int tile) {
        int s0 = tile * 16;
        const float* Db = sD + (tile & 1) * D_BUF;
        const float* redp = sred + (tile & 3) * 256;
        const float* pD = Db + srow * D_STR + dloc;
        float2 p0 = *(const float2*)(pD);
        float2 p1 = *(const float2*)(pD + D_Q);
        float2 p2 = *(const float2*)(pD + 2 * D_Q);
        float2 p3 = *(const float2*)(pD + 3 * D_Q);
        float sx = (p0.x + p1.x) + (p2.x + p3.x);
        float sy = (p0.y + p1.y) + (p2.y + p3.y);

        const float4* rr = (const float4*)(redp + srow * 16);
        float4 rA = rr[0], rB = rr[1], rC = rr[2], rD2 = rr[3];
        float rowsum = ((rA.x + rA.y) + (rA.z + rA.w))
                     + ((rB.x + rB.y) + (rB.z + rB.w))
                     + ((rC.x + rC.y) + (rC.z + rC.w))
                     + ((rD2.x + rD2.y) + (rD2.z + rD2.w));
        float inv = 1.0f / rowsum;
        float ox = sx * inv, oy = sy * inv;

        int trow = 2 * (s0 + srow) - 4;
        #pragma unroll
        for (int i = 0; i < 5; i++) {
            int t0 = trow + 2 * i;
            if ((unsigned)t0 <= 510u) {
                int tp = t0 >> 1;
                u64 xv = *(const u64*)(xp16 + tp * 64 + (dloc ^ (8 * (tp & 3))));
                float2 xa = h2f2((u32)xv);
                float2 xb = h2f2((u32)(xv >> 32));
                float w0 = skb[2 * i], w1 = skb[2 * i + 1];
                ox = fmaf(w0, xa.x, fmaf(w1, xa.y, ox));
                oy = fmaf(w0, xb.x, fmaf(w1, xb.y, oy));
            }
        }
        int sidx = s0 + srow;
        size_t ob = (((size_t)n * CC + dloc) * SS + sidx) * VV + v;
        out[ob] = ox;
        out[ob + dstg] = oy;
    };

    do_scores(0);
    __syncthreads();
    for (int i = 0; i < 16; i++) {
        if (i < 15) do_scores(i + 1);
        do_gemm(i);
        __syncthreads();
        do_epi(i);
        // no bar: epi(i) races only against buffers with different parity
        // (att 2-buf, D 2-buf, red 4-buf); all same-buffer reuse is separated
        // by at least one later __syncthreads().
    }
}

extern "C" void kernel_launch(void* const* d_in, const int* in_sizes, int n_in,
                              void* d_out, int out_size)
{
    const float* x     = (const float*)d_in[0];
    const float* W     = (const float*)d_in[1];
    const float* alpha = (const float*)d_in[2];
    const float* phi   = (const float*)d_in[3];
    const float* karr  = (const float*)d_in[4];
    float* out = (float*)d_out;

    xpose16_kernel<<<dim3(400, 2, 16), dim3(32, 8)>>>(x);

    const int smemB = SMEM_FLOATS * sizeof(float);   // 161344 bytes
    cudaFuncSetAttribute(tgatA_kernel,
                         cudaFuncAttributeMaxDynamicSharedMemorySize, smemB);
    tgatA_kernel<<<NVB, 512, smemB>>>(W, alpha, phi, karr, out);
}

// round 16
// speedup vs baseline: 2.5972x; 1.1799x over previous
#include <cuda_runtime.h>

#define CC 64
#define TT 512
#define VV 25
#define SS 256
#define NVB 400

#define ATT_STRU 260
#define D_STR 66
#define D_Q   2112                 // 32*66

#define OFF_KK  16384
#define OFF_Q   20480
#define OFF_ATT 22528              // [32][260] u32 = 8320
#define OFF_D   30848              // [4][32][66] = 8448
#define OFF_RED 39296              // 2 x 512
#define OFF_KB  40320
#define SMEM_FLOATS 40336          // 161344 bytes
#define OFF_OV  22528              // overlay: xs16 (phase1), sAl/sPh (phase2)
#define OFF_W16 26624              // overlay: w16 (phase1)

typedef unsigned long long u64;
typedef unsigned int u32;
typedef unsigned short u16;

__device__ u32   g_xT16[(size_t)NVB * TT * 32];    // [n][v][t][c-pair] fp16x2
__device__ float g_scr [(size_t)NVB * SS * CC];    // [nv][s][d] fp32

__device__ __forceinline__ u64 pk2(float a, float b) {
    u64 r; asm("mov.b64 %0, {%1,%2};" : "=l"(r) : "f"(a), "f"(b)); return r;
}
__device__ __forceinline__ u64 f2(u64 a, u64 b, u64 c) {
    u64 d; asm("fma.rn.f32x2 %0, %1, %2, %3;" : "=l"(d) : "l"(a), "l"(b), "l"(c)); return d;
}
__device__ __forceinline__ u64 ad2(u64 a, u64 b) {
    u64 d; asm("add.rn.f32x2 %0, %1, %2;" : "=l"(d) : "l"(a), "l"(b)); return d;
}
__device__ __forceinline__ float2 up2(u64 a) {
    float lo, hi; asm("mov.b64 {%0,%1}, %2;" : "=f"(lo), "=f"(hi) : "l"(a));
    return make_float2(lo, hi);
}
__device__ __forceinline__ u32 hpk(float hi, float lo) {
    u32 r; asm("cvt.rn.f16x2.f32 %0, %1, %2;" : "=r"(r) : "f"(hi), "f"(lo)); return r;
}
__device__ __forceinline__ float2 h2f2(u32 h) {
    float2 f;
    asm("{.reg .f16 l,u; mov.b32 {l,u}, %2; cvt.f32.f16 %0, l; cvt.f32.f16 %1, u;}"
        : "=f"(f.x), "=f"(f.y) : "r"(h));
    return f;
}
__device__ __forceinline__ void mma16h(float4& d, u32 a0, u32 a1, u32 a2, u32 a3,
                                       u32 b0, u32 b1) {
    asm("mma.sync.aligned.m16n8k16.row.col.f32.f16.f16.f32 "
        "{%0,%1,%2,%3},{%4,%5,%6,%7},{%8,%9},{%0,%1,%2,%3};"
        : "+f"(d.x), "+f"(d.y), "+f"(d.z), "+f"(d.w)
        : "r"(a0), "r"(a1), "r"(a2), "r"(a3), "r"(b0), "r"(b1));
}
__device__ __forceinline__ u64 shflx64(u64 v, int m) {
    u32 lo = (u32)v, hi = (u32)(v >> 32);
    lo = __shfl_xor_sync(0xffffffffu, lo, m);
    hi = __shfl_xor_sync(0xffffffffu, hi, m);
    return ((u64)hi << 32) | lo;
}

// ---------------------------------------------------------------------------
// Transpose: x[n][c][t][v] -> g_xT16[n][v][t][c-pair] (fp16x2)
// ---------------------------------------------------------------------------
__global__ void __launch_bounds__(256) xpose16_kernel(const float* __restrict__ x)
{
    __shared__ float tile[32][33];
    const int n  = blockIdx.z;
    const int c0 = blockIdx.y * 32;
    const int j0 = blockIdx.x * 32;
    const int tx = threadIdx.x, ty = threadIdx.y;

    const float* xb = x + ((size_t)n * CC + c0) * (TT * VV) + j0;
    #pragma unroll
    for (int r = 0; r < 32; r += 8)
        tile[ty + r][tx] = xb[(size_t)(ty + r) * (TT * VV) + tx];
    __syncthreads();

    const int idx = ty * 32 + tx;
    u32* ob = g_xT16 + (size_t)n * VV * TT * 32 + (c0 >> 1);
    #pragma unroll
    for (int i = 0; i < 2; i++) {
        int id = idx + i * 256;
        int j = id >> 4;
        int cp = id & 15;
        int jj = j0 + j;
        int t = jj / VV, v = jj - t * VV;
        u32 val = hpk(tile[2 * cp + 1][j], tile[2 * cp][j]);
        ob[((size_t)v * TT + t) * 32 + cp] = val;
    }
}

// ---------------------------------------------------------------------------
// Relayout: g_scr[n][v][s][d] -> out[n][d][s][v]
// block = (s-tile of 16, n); smem [p = s*25+v][d] pad 69
// ---------------------------------------------------------------------------
__global__ void __launch_bounds__(256) relayout_kernel(float* __restrict__ out)
{
    extern __shared__ float sbuf[];            // 400*69 = 27600 floats
    const int n  = blockIdx.y;
    const int s0 = blockIdx.x * 16;
    const int tid = threadIdx.x;

    for (int idx = tid; idx < 400 * 16; idx += 256) {
        int row = idx >> 4, c4 = (idx & 15) * 4;
        int v = row >> 4, s = row & 15;        // row = v*16 + s
        float4 val = *(const float4*)(g_scr + (((size_t)(n * VV + v) * SS) + s0 + s) * 64 + c4);
        float* dst = sbuf + (s * 25 + v) * 69 + c4;
        dst[0] = val.x; dst[1] = val.y; dst[2] = val.z; dst[3] = val.w;
    }
    __syncthreads();

    const int w = tid >> 5, l = tid & 31;
    for (int d = w; d < 64; d += 8) {
        float* ob = out + (((size_t)n * CC + d) * SS + s0) * 25;
        for (int c = l; c < 100; c += 32) {
            int p0 = c * 4;
            float4 val;
            val.x = sbuf[(p0 + 0) * 69 + d];
            val.y = sbuf[(p0 + 1) * 69 + d];
            val.z = sbuf[(p0 + 2) * 69 + d];
            val.w = sbuf[(p0 + 3) * 69 + d];
            *(float4*)(ob + p0) = val;
        }
    }
}

// ---------------------------------------------------------------------------
__global__ void __launch_bounds__(512, 1) tgatB_kernel(
    const float* __restrict__ W,
    const float* __restrict__ alpha, const float* __restrict__ phi,
    const float* __restrict__ karr)
{
    extern __shared__ float sm[];
    u32*   xp16 = (u32*)sm;                  // [256 tp][64 d], d ^= 8*(tp&3)
    u32*   kk16 = (u32*)(sm + OFF_KK);       // [512 t][8 jp], jp ^= t&7
    u32*   q16  = (u32*)(sm + OFF_Q);        // [256 s][8 jp], jp ^= s&7
    u32*   at16 = (u32*)(sm + OFF_ATT);      // [32 row][260 tp]
    float* sD   = sm + OFF_D;                // [4][32][66]
    float* sred = sm + OFF_RED;              // 2 x [32][16]
    float* skb  = sm + OFF_KB;
    u32*   xs16 = (u32*)(sm + OFF_OV);       // [128 lt][32 cp], cp ^= 4*(lt&7)
    u32*   w16  = (u32*)(sm + OFF_W16);      // [32 cp][64 d], d ^= 8*(cp&3)

    const int tid = threadIdx.x;
    const int nv = blockIdx.x;
    const int wid = tid >> 5, wl = tid & 31;
    const int r4 = wl >> 2, cl = wl & 3;

    // ---------- phase 0: W -> w16 fp16 c-pair packed ----------
    {
        int cp = tid >> 4;
        int d0 = (tid & 15) * 4;
        float4 wa = *(const float4*)(W + (2 * cp) * 64 + d0);
        float4 wb = *(const float4*)(W + (2 * cp + 1) * 64 + d0);
        int sw = 8 * (cp & 3);
        w16[cp * 64 + ((d0 + 0) ^ sw)] = hpk(wb.x, wa.x);
        w16[cp * 64 + ((d0 + 1) ^ sw)] = hpk(wb.y, wa.y);
        w16[cp * 64 + ((d0 + 2) ^ sw)] = hpk(wb.z, wa.z);
        w16[cp * 64 + ((d0 + 3) ^ sw)] = hpk(wb.w, wa.w);
    }
    if (tid < 16) skb[tid] = (tid < 9) ? karr[tid] : 0.0f;

    // ---------- phase 1: xp = x @ W via fp16 mma, 4 chunks of 128 t ----------
    const u32* xTb = g_xT16 + (size_t)nv * TT * 32;
    const int p1row = tid >> 2;
    const int p1q   = (tid & 3) * 8;
    uint4 ga, gb;
    {
        const u32* p = xTb + (size_t)p1row * 32 + p1q;
        ga = *(const uint4*)p; gb = *(const uint4*)(p + 4);
    }
    {
        int sw = 4 * (p1row & 7);
        u32* b = xs16 + p1row * 32;
        *(u64*)(b + ((p1q + 0) ^ sw)) = ((u64)ga.y << 32) | ga.x;
        *(u64*)(b + ((p1q + 2) ^ sw)) = ((u64)ga.w << 32) | ga.z;
        *(u64*)(b + ((p1q + 4) ^ sw)) = ((u64)gb.y << 32) | gb.x;
        *(u64*)(b + ((p1q + 6) ^ sw)) = ((u64)gb.w << 32) | gb.z;
    }
    __syncthreads();

    const int mt = wid >> 1, nh = wid & 1;
    u32 WB[4][4][2];
    #pragma unroll
    for (int nb = 0; nb < 4; nb++)
        #pragma unroll
        for (int kc = 0; kc < 4; kc++) {
            int cp = kc * 8 + cl;
            int d = nh * 32 + nb * 8 + r4;
            WB[nb][kc][0] = w16[cp * 64 + (d ^ (8 * cl))];
            WB[nb][kc][1] = w16[(cp + 4) * 64 + (d ^ (8 * cl))];
        }

    for (int ch = 0; ch < 4; ch++) {
        if (ch < 3) {
            const u32* p = xTb + (size_t)((ch + 1) * 128 + p1row) * 32 + p1q;
            ga = *(const uint4*)p; gb = *(const uint4*)(p + 4);
        }
        float4 Dx[4];
        #pragma unroll
        for (int nb = 0; nb < 4; nb++) Dx[nb] = make_float4(0.f, 0.f, 0.f, 0.f);
        const int lt0 = mt * 16 + r4;
        const int swa = 4 * r4;
        #pragma unroll
        for (int kc = 0; kc < 4; kc++) {
            u32 a0 = xs16[lt0 * 32 + ((kc * 8 + cl) ^ swa)];
            u32 a1 = xs16[(lt0 + 8) * 32 + ((kc * 8 + cl) ^ swa)];
            u32 a2 = xs16[lt0 * 32 + ((kc * 8 + cl + 4) ^ swa)];
            u32 a3 = xs16[(lt0 + 8) * 32 + ((kc * 8 + cl + 4) ^ swa)];
            #pragma unroll
            for (int nb = 0; nb < 4; nb++)
                mma16h(Dx[nb], a0, a1, a2, a3, WB[nb][kc][0], WB[nb][kc][1]);
        }
        {
            int gt = ch * 128 + mt * 16 + r4;
            int tp = gt >> 1;
            int sw = 8 * (tp & 3);
            bool even = ((r4 & 1) == 0);
            #pragma unroll
            for (int nb = 0; nb < 4; nb++) {
                int dc = nh * 32 + nb * 8 + 2 * cl;
                float o0 = __shfl_xor_sync(0xffffffffu, Dx[nb].x, 4);
                float o1 = __shfl_xor_sync(0xffffffffu, Dx[nb].y, 4);
                float o2 = __shfl_xor_sync(0xffffffffu, Dx[nb].z, 4);
                float o3 = __shfl_xor_sync(0xffffffffu, Dx[nb].w, 4);
                if (even) {
                    u32 p0 = hpk(o0, Dx[nb].x);
                    u32 p1 = hpk(o1, Dx[nb].y);
                    u32 p2 = hpk(o2, Dx[nb].z);
                    u32 p3 = hpk(o3, Dx[nb].w);
                    *(u64*)(xp16 + tp * 64 + (dc ^ sw))       = ((u64)p1 << 32) | p0;
                    *(u64*)(xp16 + (tp + 4) * 64 + (dc ^ sw)) = ((u64)p3 << 32) | p2;
                }
            }
        }
        if (ch < 3) {
            __syncthreads();
            int sw = 4 * (p1row & 7);
            u32* b = xs16 + p1row * 32;
            *(u64*)(b + ((p1q + 0) ^ sw)) = ((u64)ga.y << 32) | ga.x;
            *(u64*)(b + ((p1q + 2) ^ sw)) = ((u64)ga.w << 32) | ga.z;
            *(u64*)(b + ((p1q + 4) ^ sw)) = ((u64)gb.y << 32) | gb.x;
            *(u64*)(b + ((p1q + 6) ^ sw)) = ((u64)gb.w << 32) | gb.z;
            __syncthreads();
        }
    }
    __syncthreads();

    // ---------- phase 2: kk = xp@phi ; q = xp@alpha/16 (fp16 outputs) ----------
    float* sAl = sm + OFF_OV;
    float* sPh = sm + OFF_OV + 1024;
    for (int i = tid; i < 1024; i += 512) { sAl[i] = alpha[i] * 0.0625f; sPh[i] = phi[i]; }
    __syncthreads();
    {
        const int tp = tid >> 1, hf = tid & 1;
        const int s4 = tp & 3;
        u64 k0[8], k1[8], qa[8];
        #pragma unroll
        for (int j = 0; j < 8; j++) { k0[j] = pk2(0.f, 0.f); k1[j] = k0[j]; qa[j] = k0[j]; }
        #pragma unroll
        for (int b = 0; b < 4; b++) {
            int kb = (b ^ s4) * 8 + hf * 32;
            uint4 va = *(const uint4*)(xp16 + tp * 64 + kb);
            uint4 vb = *(const uint4*)(xp16 + tp * 64 + kb + 4);
            u32 uu[8] = {va.x, va.y, va.z, va.w, vb.x, vb.y, vb.z, vb.w};
            #pragma unroll
            for (int i = 0; i < 8; i++) {
                int d = hf * 32 + b * 8 + i;
                float2 xv = h2f2(uu[i]);
                u64 x0 = pk2(xv.x, xv.x), x1 = pk2(xv.y, xv.y);
                const ulonglong2* pp = (const ulonglong2*)(sPh + d * 16);
                ulonglong2 p0 = pp[0], p1 = pp[1], p2 = pp[2], p3 = pp[3];
                k0[0] = f2(x0, p0.x, k0[0]); k0[1] = f2(x0, p0.y, k0[1]);
                k0[2] = f2(x0, p1.x, k0[2]); k0[3] = f2(x0, p1.y, k0[3]);
                k0[4] = f2(x0, p2.x, k0[4]); k0[5] = f2(x0, p2.y, k0[5]);
                k0[6] = f2(x0, p3.x, k0[6]); k0[7] = f2(x0, p3.y, k0[7]);
                k1[0] = f2(x1, p0.x, k1[0]); k1[1] = f2(x1, p0.y, k1[1]);
                k1[2] = f2(x1, p1.x, k1[2]); k1[3] = f2(x1, p1.y, k1[3]);
                k1[4] = f2(x1, p2.x, k1[4]); k1[5] = f2(x1, p2.y, k1[5]);
                k1[6] = f2(x1, p3.x, k1[6]); k1[7] = f2(x1, p3.y, k1[7]);
                const ulonglong2* aa = (const ulonglong2*)(sAl + d * 16);
                ulonglong2 a0 = aa[0], a1 = aa[1], a2 = aa[2], a3 = aa[3];
                qa[0] = f2(x0, a0.x, qa[0]); qa[1] = f2(x0, a0.y, qa[1]);
                qa[2] = f2(x0, a1.x, qa[2]); qa[3] = f2(x0, a1.y, qa[3]);
                qa[4] = f2(x0, a2.x, qa[4]); qa[5] = f2(x0, a2.y, qa[5]);
                qa[6] = f2(x0, a3.x, qa[6]); qa[7] = f2(x0, a3.y, qa[7]);
            }
        }
        #pragma unroll
        for (int j = 0; j < 8; j++) {
            k0[j] = ad2(k0[j], shflx64(k0[j], 1));
            k1[j] = ad2(k1[j], shflx64(k1[j], 1));
            qa[j] = ad2(qa[j], shflx64(qa[j], 1));
        }
        int t0 = 2 * tp;
        if (hf == 0) {
            #pragma unroll
            for (int jp = 0; jp < 8; jp++) {
                float2 kv = up2(k0[jp]);
                kk16[t0 * 8 + (jp ^ (t0 & 7))] = hpk(kv.y, kv.x);
                float2 qv = up2(qa[jp]);
                q16[tp * 8 + (jp ^ (tp & 7))] = hpk(qv.y, qv.x);
            }
        } else {
            #pragma unroll
            for (int jp = 0; jp < 8; jp++) {
                float2 kv = up2(k1[jp]);
                kk16[(t0 + 1) * 8 + (jp ^ ((t0 + 1) & 7))] = hpk(kv.y, kv.x);
            }
        }
    }
    __syncthreads();

    // ---------- phase 3: 8 supertiles of 32 s-rows ----------
    const int w = wid;
    const int tq = w & 3, ds = w >> 2;
    const int srow = tid >> 5, dloc = (tid & 31) * 2;

    for (int st = 0; st < 8; st++) {
        const int s0 = st * 32;
        float* redp = sred + (st & 1) * 512;

        // ---- scores: warp covers t = w*32..+31, two 16-row halves ----
        #pragma unroll
        for (int h = 0; h < 2; h++) {
            int qr = s0 + h * 16 + r4;
            u32 a0 = q16[qr * 8 + (cl ^ r4)];
            u32 a1 = q16[(qr + 8) * 8 + (cl ^ r4)];
            u32 a2 = q16[qr * 8 + ((cl + 4) ^ r4)];
            u32 a3 = q16[(qr + 8) * 8 + ((cl + 4) ^ r4)];
            float4 S[4];
            #pragma unroll
            for (int nb = 0; nb < 4; nb++) {
                int t = w * 32 + nb * 8 + r4;
                u32 b0 = kk16[t * 8 + (cl ^ r4)];
                u32 b1 = kk16[t * 8 + ((cl + 4) ^ r4)];
                S[nb] = make_float4(0.f, 0.f, 0.f, 0.f);
                mma16h(S[nb], a0, a1, a2, a3, b0, b1);
            }
            float eA[8], eB[8], sumA = 0.f, sumB = 0.f;
            #pragma unroll
            for (int nb = 0; nb < 4; nb++) {
                eA[2*nb]   = __expf(S[nb].x); eA[2*nb+1] = __expf(S[nb].y);
                eB[2*nb]   = __expf(S[nb].z); eB[2*nb+1] = __expf(S[nb].w);
                sumA += eA[2*nb] + eA[2*nb+1];
                sumB += eB[2*nb] + eB[2*nb+1];
            }
            sumA += __shfl_xor_sync(0xffffffffu, sumA, 1);
            sumA += __shfl_xor_sync(0xffffffffu, sumA, 2);
            sumB += __shfl_xor_sync(0xffffffffu, sumB, 1);
            sumB += __shfl_xor_sync(0xffffffffu, sumB, 2);
            if (cl == 0) {
                redp[(h * 16 + r4) * 16 + w]       = sumA;
                redp[(h * 16 + r4 + 8) * 16 + w]   = sumB;
            }
            #pragma unroll
            for (int nb = 0; nb < 4; nb++) {
                at16[(h * 16 + r4) * ATT_STRU + w * 16 + nb * 4 + cl]     = hpk(eA[2*nb+1], eA[2*nb]);
                at16[(h * 16 + r4 + 8) * ATT_STRU + w * 16 + nb * 4 + cl] = hpk(eB[2*nb+1], eB[2*nb]);
            }
        }
        __syncthreads();                       // bar A: att + red ready

        // ---- out GEMM: warp = (tq, ds), both halves share xp B-fragments ----
        {
            float4 D[2][2];
            D[0][0] = D[0][1] = D[1][0] = D[1][1] = make_float4(0.f, 0.f, 0.f, 0.f);
            #pragma unroll 2
            for (int kc = 0; kc < 8; kc++) {
                int tpb = tq * 64 + kc * 8;
                int d0i = ds * 16 + r4;
                int swb = 8 * cl;
                u32 b00 = xp16[(tpb + cl) * 64 + (d0i ^ swb)];
                u32 b01 = xp16[(tpb + cl + 4) * 64 + (d0i ^ swb)];
                u32 b10 = xp16[(tpb + cl) * 64 + ((d0i + 8) ^ swb)];
                u32 b11 = xp16[(tpb + cl + 4) * 64 + ((d0i + 8) ^ swb)];
                #pragma unroll
                for (int h = 0; h < 2; h++) {
                    const u32* ar = at16 + (h * 16 + r4) * ATT_STRU;
                    u32 g0 = ar[tpb + cl];
                    u32 g1 = ar[8 * ATT_STRU + tpb + cl];
                    u32 g2 = ar[tpb + cl + 4];
                    u32 g3 = ar[8 * ATT_STRU + tpb + cl + 4];
                    mma16h(D[h][0], g0, g1, g2, g3, b00, b01);
                    mma16h(D[h][1], g0, g1, g2, g3, b10, b11);
                }
            }
            int c2 = 2 * cl;
            #pragma unroll
            for (int h = 0; h < 2; h++) {
                float* dp = sD + tq * D_Q + (h * 16 + r4) * D_STR + ds * 16;
                *(float2*)(dp + c2)                  = make_float2(D[h][0].x, D[h][0].y);
                *(float2*)(dp + c2 + 8 * D_STR)      = make_float2(D[h][0].z, D[h][0].w);
                *(float2*)(dp + c2 + 8)              = make_float2(D[h][1].x, D[h][1].y);
                *(float2*)(dp + c2 + 8 + 8 * D_STR)  = make_float2(D[h][1].z, D[h][1].w);
            }
        }
        __syncthreads();                       // bar B: D ready

        // ---- epilogue: two halves, coalesced scratch store ----
        #pragma unroll
        for (int h = 0; h < 2; h++) {
            int row32 = h * 16 + srow;
            const float* pD = sD + row32 * D_STR + dloc;
            float2 p0 = *(const float2*)(pD);
            float2 p1 = *(const float2*)(pD + D_Q);
            float2 p2 = *(const float2*)(pD + 2 * D_Q);
            float2 p3 = *(const float2*)(pD + 3 * D_Q);
            float sx = (p0.x + p1.x) + (p2.x + p3.x);
            float sy = (p0.y + p1.y) + (p2.y + p3.y);

            const float4* rr = (const float4*)(redp + row32 * 16);
            float4 rA = rr[0], rB = rr[1], rC = rr[2], rD2 = rr[3];
            float rowsum = ((rA.x + rA.y) + (rA.z + rA.w))
                         + ((rB.x + rB.y) + (rB.z + rB.w))
                         + ((rC.x + rC.y) + (rC.z + rC.w))
                         + ((rD2.x + rD2.y) + (rD2.z + rD2.w));
            float inv = 1.0f / rowsum;
            float ox = sx * inv, oy = sy * inv;

            int sidx = s0 + row32;
            int trow = 2 * sidx - 4;
            #pragma unroll
            for (int i = 0; i < 5; i++) {
                int t0 = trow + 2 * i;
                if ((unsigned)t0 <= 510u) {
                    int tp = t0 >> 1;
                    u64 xv = *(const u64*)(xp16 + tp * 64 + (dloc ^ (8 * (tp & 3))));
                    float2 xa = h2f2((u32)xv);
                    float2 xb = h2f2((u32)(xv >> 32));
                    float w0 = skb[2 * i], w1 = skb[2 * i + 1];
                    ox = fmaf(w0, xa.x, fmaf(w1, xa.y, ox));
                    oy = fmaf(w0, xb.x, fmaf(w1, xb.y, oy));
                }
            }
            *(float2*)(g_scr + ((size_t)nv * SS + sidx) * 64 + dloc) = make_float2(ox, oy);
        }
        // no bar: epi reads D/red; next supertile's scores write att (last
        // read before bar B) and red[(st+1)&1] (disjoint buffer); gemm(st+1)
        // writes D only after bar A(st+1), which follows every thread's epi.
    }
}

extern "C" void kernel_launch(void* const* d_in, const int* in_sizes, int n_in,
                              void* d_out, int out_size)
{
    const float* x     = (const float*)d_in[0];
    const float* W     = (const float*)d_in[1];
    const float* alpha = (const float*)d_in[2];
    const float* phi   = (const float*)d_in[3];
    const float* karr  = (const float*)d_in[4];
    float* out = (float*)d_out;

    xpose16_kernel<<<dim3(400, 2, 16), dim3(32, 8)>>>(x);

    const int smemB = SMEM_FLOATS * sizeof(float);   // 161344 bytes
    cudaFuncSetAttribute(tgatB_kernel,
                         cudaFuncAttributeMaxDynamicSharedMemorySize, smemB);
    tgatB_kernel<<<NVB, 512, smemB>>>(W, alpha, phi, karr);

    const int rsmem = 400 * 69 * sizeof(float);      // 110400 bytes
    cudaFuncSetAttribute(relayout_kernel,
                         cudaFuncAttributeMaxDynamicSharedMemorySize, rsmem);
    relayout_kernel<<<dim3(16, 16), 256, rsmem>>>(out);
}

// round 17
// speedup vs baseline: 3.1176x; 1.2004x over previous
#include <cuda_runtime.h>

#define CC 64
#define TT 512
#define VV 25
#define SS 256
#define NVB 400

#define ATT_STRU 260
#define D_STR 66
#define D_Q   2112                 // 32*66

#define OFF_KK  16384              // kk16 [512][8] u32 (phase1 overlay: xs16 [128][32])
#define OFF_Q   20480              // q16 [256][8] u32 (phase1 overlay: w16 [32][64])
#define OFF_ATT 22528              // at16 [32][260] u32 (ph1-2 overlay: xp16c [512][32])
#define OFF_D   30848              // sD [4][32][66]
#define OFF_RED 39296              // 2 x 512
#define OFF_KB  40320
#define SMEM_FLOATS 40336          // 161344 bytes
#define OFF_XPC  22528
#define OFF_PHI16 38912            // 512 u32 (overlaps red; disjoint phases)
#define OFF_AL16  39424            // 512 u32

typedef unsigned long long u64;
typedef unsigned int u32;
typedef unsigned short u16;

__device__ u32 g_xT16 [(size_t)NVB * TT * 32];   // [n][v][t][c-pair] fp16x2
__device__ u32 g_scr16[(size_t)NVB * SS * 32];   // [nv][s][d-pair] fp16x2

__device__ __forceinline__ u32 hpk(float hi, float lo) {
    u32 r; asm("cvt.rn.f16x2.f32 %0, %1, %2;" : "=r"(r) : "f"(hi), "f"(lo)); return r;
}
__device__ __forceinline__ float2 h2f2(u32 h) {
    float2 f;
    asm("{.reg .f16 l,u; mov.b32 {l,u}, %2; cvt.f32.f16 %0, l; cvt.f32.f16 %1, u;}"
        : "=f"(f.x), "=f"(f.y) : "r"(h));
    return f;
}
__device__ __forceinline__ void mma16h(float4& d, u32 a0, u32 a1, u32 a2, u32 a3,
                                       u32 b0, u32 b1) {
    asm("mma.sync.aligned.m16n8k16.row.col.f32.f16.f16.f32 "
        "{%0,%1,%2,%3},{%4,%5,%6,%7},{%8,%9},{%0,%1,%2,%3};"
        : "+f"(d.x), "+f"(d.y), "+f"(d.z), "+f"(d.w)
        : "r"(a0), "r"(a1), "r"(a2), "r"(a3), "r"(b0), "r"(b1));
}

// ---------------------------------------------------------------------------
// Transpose: x[n][c][t][v] -> g_xT16[n][v][t][c-pair] (fp16x2)
// ---------------------------------------------------------------------------
__global__ void __launch_bounds__(256) xpose16_kernel(const float* __restrict__ x)
{
    __shared__ float tile[32][33];
    const int n  = blockIdx.z;
    const int c0 = blockIdx.y * 32;
    const int j0 = blockIdx.x * 32;
    const int tx = threadIdx.x, ty = threadIdx.y;

    const float* xb = x + ((size_t)n * CC + c0) * (TT * VV) + j0;
    #pragma unroll
    for (int r = 0; r < 32; r += 8)
        tile[ty + r][tx] = xb[(size_t)(ty + r) * (TT * VV) + tx];
    __syncthreads();

    const int idx = ty * 32 + tx;
    u32* ob = g_xT16 + (size_t)n * VV * TT * 32 + (c0 >> 1);
    #pragma unroll
    for (int i = 0; i < 2; i++) {
        int id = idx + i * 256;
        int j = id >> 4;
        int cp = id & 15;
        int jj = j0 + j;
        int t = (jj * 5243) >> 17;          // jj / 25, exact for jj < 12800
        int v = jj - t * 25;
        u32 val = hpk(tile[2 * cp + 1][j], tile[2 * cp][j]);
        ob[((size_t)v * TT + t) * 32 + cp] = val;
    }
}

// ---------------------------------------------------------------------------
// Relayout: g_scr16[n][v][s][dpair] -> out[n][d][s][v]
// ---------------------------------------------------------------------------
__global__ void __launch_bounds__(256) relayout_kernel(float* __restrict__ out)
{
    extern __shared__ float sbuf[];            // 400*69 floats
    const int n  = blockIdx.y;
    const int s0 = blockIdx.x * 16;
    const int tid = threadIdx.x;

    for (int idx = tid; idx < 3200; idx += 256) {
        int row = idx >> 3;                    // v*16 + s
        int q4  = idx & 7;
        int v = row >> 4, s = row & 15;
        const uint4* src = (const uint4*)(g_scr16 +
            (((size_t)(n * VV + v) * SS) + s0 + s) * 32) + q4;
        uint4 val = *src;
        float* dst = sbuf + (s * 25 + v) * 69 + q4 * 8;
        float2 f0 = h2f2(val.x), f1 = h2f2(val.y);
        float2 f2v = h2f2(val.z), f3 = h2f2(val.w);
        dst[0] = f0.x;  dst[1] = f0.y;  dst[2] = f1.x;  dst[3] = f1.y;
        dst[4] = f2v.x; dst[5] = f2v.y; dst[6] = f3.x;  dst[7] = f3.y;
    }
    __syncthreads();

    const int w = tid >> 5, l = tid & 31;
    for (int d = w; d < 64; d += 8) {
        float* ob = out + (((size_t)n * CC + d) * SS + s0) * 25;
        for (int c = l; c < 100; c += 32) {
            int p0 = c * 4;
            float4 val;
            val.x = sbuf[(p0 + 0) * 69 + d];
            val.y = sbuf[(p0 + 1) * 69 + d];
            val.z = sbuf[(p0 + 2) * 69 + d];
            val.w = sbuf[(p0 + 3) * 69 + d];
            *(float4*)(ob + p0) = val;
        }
    }
}

// ---------------------------------------------------------------------------
__global__ void __launch_bounds__(512, 1) tgatC_kernel(
    const float* __restrict__ W,
    const float* __restrict__ alpha, const float* __restrict__ phi,
    const float* __restrict__ karr)
{
    extern __shared__ float sm[];
    u32*   xp16  = (u32*)sm;                   // [256 tp][64 d], d ^= 8*(tp&3)
    u32*   kk16  = (u32*)(sm + OFF_KK);        // [512 t][8 jp], jp ^= t&7
    u32*   q16   = (u32*)(sm + OFF_Q);         // [256 s][8 jp], jp ^= s&7
    u32*   at16  = (u32*)(sm + OFF_ATT);       // [32 row][260 tp]
    float* sD    = sm + OFF_D;                 // [4][32][66]
    float* sred  = sm + OFF_RED;               // 2 x [32][16]
    float* skb   = sm + OFF_KB;
    u32*   xs16  = (u32*)(sm + OFF_KK);        // phase1: [128 lt][32 cp], cp ^= 4*(lt&7)
    u32*   w16   = (u32*)(sm + OFF_Q);         // phase1: [32 cp][64 d], d ^= 8*(cp&3)
    u32*   xp16c = (u32*)(sm + OFF_XPC);       // ph1-2: [512 t][32 cp], cp ^= 4*(t&7)
    u32*   phi16 = (u32*)(sm + OFF_PHI16);     // [32 cp][16 j]
    u32*   al16  = (u32*)(sm + OFF_AL16);      // [32 cp][16 j]

    const int tid = threadIdx.x;
    const int nv = blockIdx.x;
    const int wid = tid >> 5, wl = tid & 31;
    const int r4 = wl >> 2, cl = wl & 3;

    // ---------- phase 0: W -> w16 fp16 c-pair packed ----------
    {
        int cp = tid >> 4;
        int d0 = (tid & 15) * 4;
        float4 wa = *(const float4*)(W + (2 * cp) * 64 + d0);
        float4 wb = *(const float4*)(W + (2 * cp + 1) * 64 + d0);
        int sw = 8 * (cp & 3);
        w16[cp * 64 + ((d0 + 0) ^ sw)] = hpk(wb.x, wa.x);
        w16[cp * 64 + ((d0 + 1) ^ sw)] = hpk(wb.y, wa.y);
        w16[cp * 64 + ((d0 + 2) ^ sw)] = hpk(wb.z, wa.z);
        w16[cp * 64 + ((d0 + 3) ^ sw)] = hpk(wb.w, wa.w);
    }
    if (tid < 16) skb[tid] = (tid < 9) ? karr[tid] : 0.0f;

    // ---------- phase 1: xp = x @ W via fp16 mma, 4 chunks of 128 t ----------
    // emits BOTH xp16 (t-pair pack, for gemm-B/epilogue) and xp16c (c-pair pack,
    // for phase-2 mma A-fragments).
    const u32* xTb = g_xT16 + (size_t)nv * TT * 32;
    const int p1row = tid >> 2;
    const int p1q   = (tid & 3) * 8;
    uint4 ga, gb;
    {
        const u32* p = xTb + (size_t)p1row * 32 + p1q;
        ga = *(const uint4*)p; gb = *(const uint4*)(p + 4);
    }
    {
        int sw = 4 * (p1row & 7);
        u32* b = xs16 + p1row * 32;
        *(u64*)(b + ((p1q + 0) ^ sw)) = ((u64)ga.y << 32) | ga.x;
        *(u64*)(b + ((p1q + 2) ^ sw)) = ((u64)ga.w << 32) | ga.z;
        *(u64*)(b + ((p1q + 4) ^ sw)) = ((u64)gb.y << 32) | gb.x;
        *(u64*)(b + ((p1q + 6) ^ sw)) = ((u64)gb.w << 32) | gb.z;
    }
    __syncthreads();

    const int mt = wid >> 1, nh = wid & 1;
    u32 WB[4][4][2];
    #pragma unroll
    for (int nb = 0; nb < 4; nb++)
        #pragma unroll
        for (int kc = 0; kc < 4; kc++) {
            int cp = kc * 8 + cl;
            int d = nh * 32 + nb * 8 + r4;
            WB[nb][kc][0] = w16[cp * 64 + (d ^ (8 * cl))];
            WB[nb][kc][1] = w16[(cp + 4) * 64 + (d ^ (8 * cl))];
        }

    for (int ch = 0; ch < 4; ch++) {
        if (ch < 3) {
            const u32* p = xTb + (size_t)((ch + 1) * 128 + p1row) * 32 + p1q;
            ga = *(const uint4*)p; gb = *(const uint4*)(p + 4);
        }
        float4 Dx[4];
        #pragma unroll
        for (int nb = 0; nb < 4; nb++) Dx[nb] = make_float4(0.f, 0.f, 0.f, 0.f);
        const int lt0 = mt * 16 + r4;
        const int swa = 4 * r4;
        #pragma unroll
        for (int kc = 0; kc < 4; kc++) {
            u32 a0 = xs16[lt0 * 32 + ((kc * 8 + cl) ^ swa)];
            u32 a1 = xs16[(lt0 + 8) * 32 + ((kc * 8 + cl) ^ swa)];
            u32 a2 = xs16[lt0 * 32 + ((kc * 8 + cl + 4) ^ swa)];
            u32 a3 = xs16[(lt0 + 8) * 32 + ((kc * 8 + cl + 4) ^ swa)];
            #pragma unroll
            for (int nb = 0; nb < 4; nb++)
                mma16h(Dx[nb], a0, a1, a2, a3, WB[nb][kc][0], WB[nb][kc][1]);
        }
        // xp16c stores: lane owns d-adjacent pairs natively
        {
            int tA = ch * 128 + mt * 16 + r4;
            int tB = tA + 8;
            #pragma unroll
            for (int nb = 0; nb < 4; nb++) {
                int cp = nh * 16 + nb * 4 + cl;
                xp16c[tA * 32 + (cp ^ (4 * r4))] = hpk(Dx[nb].y, Dx[nb].x);
                xp16c[tB * 32 + (cp ^ (4 * r4))] = hpk(Dx[nb].w, Dx[nb].z);
            }
        }
        // xp16 t-pair stores (shfl pack)
        {
            int gt = ch * 128 + mt * 16 + r4;
            int tp = gt >> 1;
            int sw = 8 * (tp & 3);
            bool even = ((r4 & 1) == 0);
            #pragma unroll
            for (int nb = 0; nb < 4; nb++) {
                int dc = nh * 32 + nb * 8 + 2 * cl;
                float o0 = __shfl_xor_sync(0xffffffffu, Dx[nb].x, 4);
                float o1 = __shfl_xor_sync(0xffffffffu, Dx[nb].y, 4);
                float o2 = __shfl_xor_sync(0xffffffffu, Dx[nb].z, 4);
                float o3 = __shfl_xor_sync(0xffffffffu, Dx[nb].w, 4);
                if (even) {
                    u32 p0 = hpk(o0, Dx[nb].x);
                    u32 p1 = hpk(o1, Dx[nb].y);
                    u32 p2 = hpk(o2, Dx[nb].z);
                    u32 p3 = hpk(o3, Dx[nb].w);
                    *(u64*)(xp16 + tp * 64 + (dc ^ sw))       = ((u64)p1 << 32) | p0;
                    *(u64*)(xp16 + (tp + 4) * 64 + (dc ^ sw)) = ((u64)p3 << 32) | p2;
                }
            }
        }
        if (ch < 3) {
            __syncthreads();
            int sw = 4 * (p1row & 7);
            u32* b = xs16 + p1row * 32;
            *(u64*)(b + ((p1q + 0) ^ sw)) = ((u64)ga.y << 32) | ga.x;
            *(u64*)(b + ((p1q + 2) ^ sw)) = ((u64)ga.w << 32) | ga.z;
            *(u64*)(b + ((p1q + 4) ^ sw)) = ((u64)gb.y << 32) | gb.x;
            *(u64*)(b + ((p1q + 6) ^ sw)) = ((u64)gb.w << 32) | gb.z;
            __syncthreads();
        }
    }
    __syncthreads();                         // xp16 + xp16c complete; xs16/w16 dead

    // ---------- phase 2: kk = xp@phi, q = xp@alpha/16 via fp16 mma ----------
    {
        int cp = tid >> 4, j = tid & 15;
        phi16[cp * 16 + j] = hpk(phi[(2 * cp + 1) * 16 + j], phi[(2 * cp) * 16 + j]);
        al16[cp * 16 + j]  = hpk(alpha[(2 * cp + 1) * 16 + j] * 0.0625f,
                                 alpha[(2 * cp) * 16 + j] * 0.0625f);
    }
    __syncthreads();
    {
        u32 bp[4][2][2], ba[4][2][2];
        #pragma unroll
        for (int kc = 0; kc < 4; kc++)
            #pragma unroll
            for (int n = 0; n < 2; n++) {
                bp[kc][n][0] = phi16[(kc * 8 + cl) * 16 + n * 8 + r4];
                bp[kc][n][1] = phi16[(kc * 8 + cl + 4) * 16 + n * 8 + r4];
                ba[kc][n][0] = al16[(kc * 8 + cl) * 16 + n * 8 + r4];
                ba[kc][n][1] = al16[(kc * 8 + cl + 4) * 16 + n * 8 + r4];
            }
        #pragma unroll
        for (int ti = 0; ti < 2; ti++) {
            int t0 = (2 * wid + ti) * 16;
            float4 Dk[2], Dq[2];
            Dk[0] = Dk[1] = Dq[0] = Dq[1] = make_float4(0.f, 0.f, 0.f, 0.f);
            const int sw = 4 * r4;
            #pragma unroll
            for (int kc = 0; kc < 4; kc++) {
                u32 a0 = xp16c[(t0 + r4) * 32 + ((kc * 8 + cl) ^ sw)];
                u32 a1 = xp16c[(t0 + 8 + r4) * 32 + ((kc * 8 + cl) ^ sw)];
                u32 a2 = xp16c[(t0 + r4) * 32 + ((kc * 8 + cl + 4) ^ sw)];
                u32 a3 = xp16c[(t0 + 8 + r4) * 32 + ((kc * 8 + cl + 4) ^ sw)];
                #pragma unroll
                for (int n = 0; n < 2; n++) {
                    mma16h(Dk[n], a0, a1, a2, a3, bp[kc][n][0], bp[kc][n][1]);
                    mma16h(Dq[n], a0, a1, a2, a3, ba[kc][n][0], ba[kc][n][1]);
                }
            }
            int tA = t0 + r4, tB = t0 + 8 + r4;
            #pragma unroll
            for (int n = 0; n < 2; n++) {
                int jp = n * 4 + cl;
                kk16[tA * 8 + (jp ^ (tA & 7))] = hpk(Dk[n].y, Dk[n].x);
                kk16[tB * 8 + (jp ^ (tB & 7))] = hpk(Dk[n].w, Dk[n].z);
            }
            if ((r4 & 1) == 0) {
                int sA = tA >> 1, sB = tB >> 1;
                #pragma unroll
                for (int n = 0; n < 2; n++) {
                    int jp = n * 4 + cl;
                    q16[sA * 8 + (jp ^ (sA & 7))] = hpk(Dq[n].y, Dq[n].x);
                    q16[sB * 8 + (jp ^ (sB & 7))] = hpk(Dq[n].w, Dq[n].z);
                }
            }
        }
    }
    __syncthreads();

    // ---------- phase 3: 8 supertiles of 32 s-rows ----------
    const int w = wid;
    const int tq = w & 3, ds = w >> 2;
    const int srow = tid >> 5, dloc = (tid & 31) * 2;

    for (int st = 0; st < 8; st++) {
        const int s0 = st * 32;
        float* redp = sred + (st & 1) * 512;

        // ---- scores: warp covers t = w*32..+31; kk b-frags hoisted ----
        u32 bk0[4], bk1[4];
        #pragma unroll
        for (int nb = 0; nb < 4; nb++) {
            int t = w * 32 + nb * 8 + r4;
            bk0[nb] = kk16[t * 8 + (cl ^ r4)];
            bk1[nb] = kk16[t * 8 + ((cl + 4) ^ r4)];
        }
        #pragma unroll
        for (int h = 0; h < 2; h++) {
            int qr = s0 + h * 16 + r4;
            u32 a0 = q16[qr * 8 + (cl ^ r4)];
            u32 a1 = q16[(qr + 8) * 8 + (cl ^ r4)];
            u32 a2 = q16[qr * 8 + ((cl + 4) ^ r4)];
            u32 a3 = q16[(qr + 8) * 8 + ((cl + 4) ^ r4)];
            float4 S[4];
            #pragma unroll
            for (int nb = 0; nb < 4; nb++) {
                S[nb] = make_float4(0.f, 0.f, 0.f, 0.f);
                mma16h(S[nb], a0, a1, a2, a3, bk0[nb], bk1[nb]);
            }
            float eA[8], eB[8], sumA = 0.f, sumB = 0.f;
            #pragma unroll
            for (int nb = 0; nb < 4; nb++) {
                eA[2*nb]   = __expf(S[nb].x); eA[2*nb+1] = __expf(S[nb].y);
                eB[2*nb]   = __expf(S[nb].z); eB[2*nb+1] = __expf(S[nb].w);
                sumA += eA[2*nb] + eA[2*nb+1];
                sumB += eB[2*nb] + eB[2*nb+1];
            }
            sumA += __shfl_xor_sync(0xffffffffu, sumA, 1);
            sumA += __shfl_xor_sync(0xffffffffu, sumA, 2);
            sumB += __shfl_xor_sync(0xffffffffu, sumB, 1);
            sumB += __shfl_xor_sync(0xffffffffu, sumB, 2);
            if (cl == 0) {
                redp[(h * 16 + r4) * 16 + w]     = sumA;
                redp[(h * 16 + r4 + 8) * 16 + w] = sumB;
            }
            #pragma unroll
            for (int nb = 0; nb < 4; nb++) {
                at16[(h * 16 + r4) * ATT_STRU + w * 16 + nb * 4 + cl]     = hpk(eA[2*nb+1], eA[2*nb]);
                at16[(h * 16 + r4 + 8) * ATT_STRU + w * 16 + nb * 4 + cl] = hpk(eB[2*nb+1], eB[2*nb]);
            }
        }
        __syncthreads();                       // bar A: att + red ready

        // ---- out GEMM: warp = (tq, ds), halves share xp B-fragments ----
        {
            float4 D[2][2];
            D[0][0] = D[0][1] = D[1][0] = D[1][1] = make_float4(0.f, 0.f, 0.f, 0.f);
            #pragma unroll 2
            for (int kc = 0; kc < 8; kc++) {
                int tpb = tq * 64 + kc * 8;
                int d0i = ds * 16 + r4;
                int swb = 8 * cl;
                u32 b00 = xp16[(tpb + cl) * 64 + (d0i ^ swb)];
                u32 b01 = xp16[(tpb + cl + 4) * 64 + (d0i ^ swb)];
                u32 b10 = xp16[(tpb + cl) * 64 + ((d0i + 8) ^ swb)];
                u32 b11 = xp16[(tpb + cl + 4) * 64 + ((d0i + 8) ^ swb)];
                #pragma unroll
                for (int h = 0; h < 2; h++) {
                    const u32* ar = at16 + (h * 16 + r4) * ATT_STRU;
                    u32 g0 = ar[tpb + cl];
                    u32 g1 = ar[8 * ATT_STRU + tpb + cl];
                    u32 g2 = ar[tpb + cl + 4];
                    u32 g3 = ar[8 * ATT_STRU + tpb + cl + 4];
                    mma16h(D[h][0], g0, g1, g2, g3, b00, b01);
                    mma16h(D[h][1], g0, g1, g2, g3, b10, b11);
                }
            }
            int c2 = 2 * cl;
            #pragma unroll
            for (int h = 0; h < 2; h++) {
                float* dp = sD + tq * D_Q + (h * 16 + r4) * D_STR + ds * 16;
                *(float2*)(dp + c2)                  = make_float2(D[h][0].x, D[h][0].y);
                *(float2*)(dp + c2 + 8 * D_STR)      = make_float2(D[h][0].z, D[h][0].w);
                *(float2*)(dp + c2 + 8)              = make_float2(D[h][1].x, D[h][1].y);
                *(float2*)(dp + c2 + 8 + 8 * D_STR)  = make_float2(D[h][1].z, D[h][1].w);
            }
        }
        __syncthreads();                       // bar B: D ready

        // ---- epilogue: reduce quarters, normalize, add band, fp16 store ----
        #pragma unroll
        for (int h = 0; h < 2; h++) {
            int row32 = h * 16 + srow;
            const float* pD = sD + row32 * D_STR + dloc;
            float2 p0 = *(const float2*)(pD);
            float2 p1 = *(const float2*)(pD + D_Q);
            float2 p2 = *(const float2*)(pD + 2 * D_Q);
            float2 p3 = *(const float2*)(pD + 3 * D_Q);
            float sx = (p0.x + p1.x) + (p2.x + p3.x);
            float sy = (p0.y + p1.y) + (p2.y + p3.y);

            const float4* rr = (const float4*)(redp + row32 * 16);
            float4 rA = rr[0], rB = rr[1], rC = rr[2], rD2 = rr[3];
            float rowsum = ((rA.x + rA.y) + (rA.z + rA.w))
                         + ((rB.x + rB.y) + (rB.z + rB.w))
                         + ((rC.x + rC.y) + (rC.z + rC.w))
                         + ((rD2.x + rD2.y) + (rD2.z + rD2.w));
            float inv = 1.0f / rowsum;
            float ox = sx * inv, oy = sy * inv;

            int sidx = s0 + row32;
            int trow = 2 * sidx - 4;
            #pragma unroll
            for (int i = 0; i < 5; i++) {
                int t0 = trow + 2 * i;
                if ((unsigned)t0 <= 510u) {
                    int tp = t0 >> 1;
                    u64 xv = *(const u64*)(xp16 + tp * 64 + (dloc ^ (8 * (tp & 3))));
                    float2 xa = h2f2((u32)xv);
                    float2 xb = h2f2((u32)(xv >> 32));
                    float w0 = skb[2 * i], w1 = skb[2 * i + 1];
                    ox = fmaf(w0, xa.x, fmaf(w1, xa.y, ox));
                    oy = fmaf(w0, xb.x, fmaf(w1, xb.y, oy));
                }
            }
            g_scr16[((size_t)nv * SS + sidx) * 32 + (tid & 31)] = hpk(oy, ox);
        }
        // no bar: epi reads D/red; next supertile's scores write att (last
        // read before bar B) and red[(st+1)&1] (disjoint buffer); gemm(st+1)
        // writes D only after bar A(st+1), which follows every thread's epi.
    }
}

extern "C" void kernel_launch(void* const* d_in, const int* in_sizes, int n_in,
                              void* d_out, int out_size)
{
    const float* x     = (const float*)d_in[0];
    const float* W     = (const float*)d_in[1];
    const float* alpha = (const float*)d_in[2];
    const float* phi   = (const float*)d_in[3];
    const float* karr  = (const float*)d_in[4];
    float* out = (float*)d_out;

    xpose16_kernel<<<dim3(400, 2, 16), dim3(32, 8)>>>(x);

    const int smemB = SMEM_FLOATS * sizeof(float);   // 161344 bytes
    cudaFuncSetAttribute(tgatC_kernel,
                         cudaFuncAttributeMaxDynamicSharedMemorySize, smemB);
    tgatC_kernel<<<NVB, 512, smemB>>>(W, alpha, phi, karr);

    const int rsmem = 400 * 69 * sizeof(float);      // 110400 bytes
    cudaFuncSetAttribute(relayout_kernel,
                         cudaFuncAttributeMaxDynamicSharedMemorySize, rsmem);
    relayout_kernel<<<dim3(16, 16), 256, rsmem>>>(out);
}